// round 3
// baseline (speedup 1.0000x reference)
#include <cuda_runtime.h>
#include <math.h>

#define HEADS 8
#define DHEAD 32
#define DMODEL 256
#define NNODE 20000
#define ELOCAL 80000
#define EBOND 60000
#define EGLOBAL 400000
#define SCALE 0.17677669529663687f  // 1/sqrt(32)

// ---------------- scratch (device globals; no allocation allowed) ----------
__device__ float g_q[(size_t)NNODE * 512];
__device__ float g_k[(size_t)NNODE * 512];   // global half already includes deg_emb
__device__ float g_v[(size_t)NNODE * 512];
__device__ float g_ab[(size_t)EBOND * 256];  // attention_bond
__device__ float g_vb[(size_t)EBOND * 256];  // value_bond
__device__ float g_lacc[(size_t)NNODE * 256];
__device__ float g_gacc[(size_t)NNODE * 256];
__device__ float g_lsum[(size_t)NNODE * HEADS];
__device__ float g_gsum[(size_t)NNODE * HEADS];

// ---------------- zero accumulators ----------------------------------------
__global__ void zero_kernel() {
    int i = blockIdx.x * blockDim.x + threadIdx.x;
    if (i < NNODE * 256) { g_lacc[i] = 0.f; g_gacc[i] = 0.f; }
    if (i < NNODE * HEADS) { g_lsum[i] = 0.f; g_gsum[i] = 0.f; }
}

// ---------------- fused QKV GEMM (A shared) ---------------------------------
// q = f_node@Wq + bq ; k = f_node@Wk + bk (+deg_emb[deg] on cols 256..511)
// v = f_node@Wv + bv.  M=NNODE, K=256, NN=512.
#define BM 64
#define BN 64
#define BK 16

__global__ void qkv_gemm(const float* __restrict__ A,
                         const float* __restrict__ Wq, const float* __restrict__ bq,
                         const float* __restrict__ Wk, const float* __restrict__ bk,
                         const float* __restrict__ Wv, const float* __restrict__ bv,
                         const int* __restrict__ deg, const float* __restrict__ deg_emb)
{
    __shared__ float As[BK][BM];
    __shared__ float Bq[BK][BN], Bk[BK][BN], Bv[BK][BN];
    const int K = 256, NN = 512;
    const int m0 = blockIdx.y * BM, n0 = blockIdx.x * BN;
    const int tid = threadIdx.x;
    float aq[4][4] = {}, ak[4][4] = {}, av[4][4] = {};
    const int ty = tid >> 4, tx = tid & 15;

    for (int k0 = 0; k0 < K; k0 += BK) {
#pragma unroll
        for (int i = 0; i < 4; i++) {
            int idx = tid + i * 256;
            int m = idx >> 4, kk = idx & 15;
            int gm = m0 + m;
            As[kk][m] = (gm < NNODE) ? A[(size_t)gm * K + k0 + kk] : 0.f;
        }
#pragma unroll
        for (int i = 0; i < 4; i++) {
            int idx = tid + i * 256;
            int kk = idx >> 6, n = idx & 63;
            size_t off = (size_t)(k0 + kk) * NN + n0 + n;
            Bq[kk][n] = Wq[off];
            Bk[kk][n] = Wk[off];
            Bv[kk][n] = Wv[off];
        }
        __syncthreads();
#pragma unroll
        for (int kk = 0; kk < BK; kk++) {
            float4 a4 = *(const float4*)(&As[kk][ty * 4]);
            float4 q4 = *(const float4*)(&Bq[kk][tx * 4]);
            float4 k4 = *(const float4*)(&Bk[kk][tx * 4]);
            float4 v4 = *(const float4*)(&Bv[kk][tx * 4]);
            float a[4] = {a4.x, a4.y, a4.z, a4.w};
            float qb[4] = {q4.x, q4.y, q4.z, q4.w};
            float kb[4] = {k4.x, k4.y, k4.z, k4.w};
            float vb[4] = {v4.x, v4.y, v4.z, v4.w};
#pragma unroll
            for (int i = 0; i < 4; i++)
#pragma unroll
                for (int j = 0; j < 4; j++) {
                    aq[i][j] += a[i] * qb[j];
                    ak[i][j] += a[i] * kb[j];
                    av[i][j] += a[i] * vb[j];
                }
        }
        __syncthreads();
    }
#pragma unroll
    for (int i = 0; i < 4; i++) {
        int gm = m0 + ty * 4 + i;
        if (gm >= NNODE) continue;
        int dg = deg[gm];
#pragma unroll
        for (int j = 0; j < 4; j++) {
            int gn = n0 + tx * 4 + j;
            size_t off = (size_t)gm * 512 + gn;
            g_q[off] = aq[i][j] + bq[gn];
            float kv = ak[i][j] + bk[gn];
            if (gn >= 256) kv += deg_emb[(size_t)dg * 256 + (gn - 256)];
            g_k[off] = kv;
            g_v[off] = av[i][j] + bv[gn];
        }
    }
}

// ---------------- generic 64x64 GEMM with mode-specific A-load / store ------
// MODE 1: bond_emb   (A=f_bond M x 256, B 256x512) -> split g_ab / g_vb
// MODE 2: out        (A = normalized [lacc | gacc], K=512, NN=256) -> C
// MODE 3: bond_update(A = [f_bond | out[src]], K=512, NN=256) -> C
template <int MODE>
__global__ void gemm64(int M, int K, int NN,
                       const float* __restrict__ A,
                       const float* __restrict__ B,
                       const float* __restrict__ bias,
                       float* __restrict__ C,
                       const int* __restrict__ idx,
                       const float* __restrict__ extra)
{
    __shared__ float As[BK][BM];
    __shared__ float Bs[BK][BN];
    const int m0 = blockIdx.y * BM, n0 = blockIdx.x * BN;
    const int tid = threadIdx.x;
    const int ty = tid >> 4, tx = tid & 15;
    float acc[4][4] = {};

    for (int k0 = 0; k0 < K; k0 += BK) {
#pragma unroll
        for (int i = 0; i < 4; i++) {
            int lidx = tid + i * 256;
            int m = lidx >> 4, kk = lidx & 15;
            int gm = m0 + m, gk = k0 + kk;
            float aval = 0.f;
            if (gm < M) {
                if (MODE == 2) {
                    if (gk < 256) {
                        float s = g_lsum[gm * HEADS + (gk >> 5)];
                        aval = (s > 0.f) ? g_lacc[(size_t)gm * 256 + gk] / s : 0.f;
                    } else {
                        int jj = gk - 256;
                        float s = g_gsum[gm * HEADS + (jj >> 5)];
                        aval = (s > 0.f) ? g_gacc[(size_t)gm * 256 + jj] / s : 0.f;
                    }
                } else if (MODE == 3) {
                    aval = (gk < 256) ? A[(size_t)gm * 256 + gk]
                                      : extra[(size_t)idx[gm] * 256 + (gk - 256)];
                } else {
                    aval = A[(size_t)gm * K + gk];
                }
            }
            As[kk][m] = aval;
        }
#pragma unroll
        for (int i = 0; i < 4; i++) {
            int lidx = tid + i * 256;
            int kk = lidx >> 6, n = lidx & 63;
            Bs[kk][n] = B[(size_t)(k0 + kk) * NN + n0 + n];
        }
        __syncthreads();
#pragma unroll
        for (int kk = 0; kk < BK; kk++) {
            float4 a4 = *(const float4*)(&As[kk][ty * 4]);
            float4 b4 = *(const float4*)(&Bs[kk][tx * 4]);
            float a[4] = {a4.x, a4.y, a4.z, a4.w};
            float b[4] = {b4.x, b4.y, b4.z, b4.w};
#pragma unroll
            for (int i = 0; i < 4; i++)
#pragma unroll
                for (int j = 0; j < 4; j++) acc[i][j] += a[i] * b[j];
        }
        __syncthreads();
    }
#pragma unroll
    for (int i = 0; i < 4; i++) {
        int gm = m0 + ty * 4 + i;
        if (gm >= M) continue;
#pragma unroll
        for (int j = 0; j < 4; j++) {
            int gn = n0 + tx * 4 + j;
            float val = acc[i][j] + bias[gn];
            if (MODE == 1) {
                if (gn < 256) g_ab[(size_t)gm * 256 + gn] = val;
                else          g_vb[(size_t)gm * 256 + (gn - 256)] = val;
            } else {
                C[(size_t)gm * NN + gn] = val;
            }
        }
    }
}

// ---------------- local attention (one block = one edge) --------------------
__global__ void local_att(const int* __restrict__ bond_idx)
{
    int e = blockIdx.x;
    int t = threadIdx.x;  // 0..255 : head = t>>5, dim = t&31
    int src = __ldg(&bond_idx[e]);
    int dst = __ldg(&bond_idx[ELOCAL + e]);
    float qv = g_q[(size_t)dst * 512 + t];
    float kv = g_k[(size_t)src * 512 + t];
    float vv = g_v[(size_t)src * 512 + t];
    float prod = qv * kv;
    if (e < EBOND) {
        prod += g_ab[(size_t)e * 256 + t];
        vv   += g_vb[(size_t)e * 256 + t];
    }
    float s = prod;
#pragma unroll
    for (int o = 16; o; o >>= 1) s += __shfl_xor_sync(0xffffffffu, s, o);
    float es = expf(s * SCALE);
    atomicAdd(&g_lacc[(size_t)dst * 256 + t], es * vv);
    if ((t & 31) == 0) atomicAdd(&g_lsum[dst * HEADS + (t >> 5)], es);
}

// ---------------- global attention (one block = one edge) -------------------
__global__ void global_att(const int* __restrict__ qi, const int* __restrict__ ki,
                           const int* __restrict__ dist, const float* __restrict__ dist_emb)
{
    int e = blockIdx.x;
    int t = threadIdx.x;
    int q = __ldg(&qi[e]);
    int k = __ldg(&ki[e]);
    int dd = __ldg(&dist[e]);
    float prod = g_q[(size_t)q * 512 + 256 + t] * g_k[(size_t)k * 512 + 256 + t]
               + __ldg(&dist_emb[(size_t)dd * 256 + t]);
    if (e < EBOND) prod += g_ab[(size_t)e * 256 + t];
    float s = prod;
#pragma unroll
    for (int o = 16; o; o >>= 1) s += __shfl_xor_sync(0xffffffffu, s, o);
    float es = expf(s * SCALE);
    float vv = g_v[(size_t)k * 512 + 256 + t];
    atomicAdd(&g_gacc[(size_t)q * 256 + t], es * vv);
    if ((t & 31) == 0) atomicAdd(&g_gsum[q * HEADS + (t >> 5)], es);
}

// ---------------- launch -----------------------------------------------------
extern "C" void kernel_launch(void* const* d_in, const int* in_sizes, int n_in,
                              void* d_out, int out_size)
{
    const float* f_node   = (const float*)d_in[0];
    const float* f_bond   = (const float*)d_in[1];
    const int*   deg      = (const int*)d_in[2];
    const int*   dist     = (const int*)d_in[3];
    const int*   bond_idx = (const int*)d_in[4];
    const int*   query_ix = (const int*)d_in[5];
    const int*   key_ix   = (const int*)d_in[6];
    // d_in[7] attention_bond_idx == arange(E_BOND) (positional identity)
    const float* deg_emb  = (const float*)d_in[8];
    const float* dist_emb = (const float*)d_in[9];
    const float* Wq_w = (const float*)d_in[10]; const float* Wq_b = (const float*)d_in[11];
    const float* Wk_w = (const float*)d_in[12]; const float* Wk_b = (const float*)d_in[13];
    const float* Wv_w = (const float*)d_in[14]; const float* Wv_b = (const float*)d_in[15];
    const float* out_w = (const float*)d_in[16]; const float* out_b = (const float*)d_in[17];
    const float* be_w = (const float*)d_in[18]; const float* be_b = (const float*)d_in[19];
    const float* bu_w = (const float*)d_in[20]; const float* bu_b = (const float*)d_in[21];

    float* out      = (float*)d_out;                      // (NNODE, 256)
    float* bond_out = out + (size_t)NNODE * 256;          // (EBOND, 256)

    zero_kernel<<<(NNODE * 256 + 255) / 256, 256>>>();

    // QKV: M=NNODE, K=256, NN=512
    qkv_gemm<<<dim3(512 / BN, (NNODE + BM - 1) / BM), 256>>>(
        f_node, Wq_w, Wq_b, Wk_w, Wk_b, Wv_w, Wv_b, deg, deg_emb);

    // bond embedding: M=EBOND, K=256, NN=512 -> g_ab / g_vb
    gemm64<1><<<dim3(512 / BN, (EBOND + BM - 1) / BM), 256>>>(
        EBOND, 256, 512, f_bond, be_w, be_b, nullptr, nullptr, nullptr);

    local_att<<<ELOCAL, 256>>>(bond_idx);
    global_att<<<EGLOBAL, 256>>>(query_ix, key_ix, dist, dist_emb);

    // out = [lacc/lsum | gacc/gsum] @ out_w + out_b : M=NNODE, K=512, NN=256
    gemm64<2><<<dim3(256 / BN, (NNODE + BM - 1) / BM), 256>>>(
        NNODE, 512, 256, nullptr, out_w, out_b, out, nullptr, nullptr);

    // bond_out = [f_bond | out[src]] @ bu_w + bu_b : M=EBOND, K=512, NN=256
    gemm64<3><<<dim3(256 / BN, (EBOND + BM - 1) / BM), 256>>>(
        EBOND, 512, 256, f_bond, bu_w, bu_b, bond_out, bond_idx, out);
}

// round 9
// speedup vs baseline: 1.0864x; 1.0864x over previous
#include <cuda_runtime.h>
#include <cuda_bf16.h>
#include <mma.h>
#include <math.h>

using namespace nvcuda;

#define HEADS 8
#define DHEAD 32
#define DMODEL 256
#define NNODE 20000
#define ELOCAL 80000
#define EBOND 60000
#define EGLOBAL 400000
#define SCALE 0.17677669529663687f  // 1/sqrt(32)

// ---------------- scratch (device globals; no allocation allowed) ----------
// NOTE: these must NEVER be passed as kernel arguments from host code — a
// __device__ symbol referenced in host code is the HOST shadow address, and
// GB300's ATS dereferences it silently (that was the R4-R6 bug). All access
// is from device code via the MODE template.
__device__ float g_q[(size_t)NNODE * 512];
__device__ float g_k[(size_t)NNODE * 512];   // global half already includes deg_emb
__device__ float g_v[(size_t)NNODE * 512];
__device__ float g_ab[(size_t)EBOND * 256];  // attention_bond
__device__ float g_vb[(size_t)EBOND * 256];  // value_bond
__device__ float g_lacc[(size_t)NNODE * 256];
__device__ float g_gacc[(size_t)NNODE * 256];
__device__ float g_lsum[(size_t)NNODE * HEADS];
__device__ float g_gsum[(size_t)NNODE * HEADS];

// ---------------- zero accumulators ----------------------------------------
__global__ void zero_kernel() {
    int i = blockIdx.x * blockDim.x + threadIdx.x;
    if (i < NNODE * 256) { g_lacc[i] = 0.f; g_gacc[i] = 0.f; }
    if (i < NNODE * HEADS) { g_lsum[i] = 0.f; g_gsum[i] = 0.f; }
}

// ---------------- wmma split-bf16 GEMM ---------------------------------------
// Block tile 128x128x16, 256 threads = 8 warps (4m x 2n), warp tile 32x64
// = 2x4 wmma 16x16x16 fragments. 3-term bf16 split:
//   acc += Ahi*Bhi + Alo*Bhi + Ahi*Blo   (~1e-5 relative)
//
// MODE 0: A=param, C -> g_q (device symbol)
// MODE 1: A=param (f_node), C -> g_k, epilogue adds deg_emb[deg[row]] cols>=256
// MODE 5: A=param, C -> g_v
// MODE 2: A=param (f_bond), split store: cols<256 -> g_ab, else -> g_vb
// MODE 3: A = normalized [lacc | gacc] (K=512), C = param (d_out)
// MODE 4: A = [f_bond | extra[idx[row]]] (K=512), C = param (d_out)
#define BMT 128
#define BNT 128
#define ALD 24    // A smem leading dim (bf16): 48B, multiple of 16B
#define BLD 136   // B smem leading dim (bf16): 272B, multiple of 16B

template<int MODE>
__device__ __forceinline__ float loadA(int gm, int gk, int M, int K,
                                       const float* __restrict__ A,
                                       const int* __restrict__ idx,
                                       const float* __restrict__ extra)
{
    if (gm >= M) return 0.f;
    if (MODE == 3) {
        if (gk < 256) {
            float su = g_lsum[gm * HEADS + (gk >> 5)];
            return (su > 0.f) ? g_lacc[(size_t)gm * 256 + gk] / su : 0.f;
        } else {
            int jj = gk - 256;
            float su = g_gsum[gm * HEADS + (jj >> 5)];
            return (su > 0.f) ? g_gacc[(size_t)gm * 256 + jj] / su : 0.f;
        }
    } else if (MODE == 4) {
        return (gk < 256) ? A[(size_t)gm * 256 + gk]
                          : extra[(size_t)idx[gm] * 256 + (gk - 256)];
    } else {
        return A[(size_t)gm * K + gk];
    }
}

template<int MODE>
__global__ void __launch_bounds__(256) tgemm(
    int M, int K, int NN,
    const float* __restrict__ A, const float* __restrict__ B,
    const float* __restrict__ bias, float* __restrict__ Cparam,
    const int* __restrict__ idx, const float* __restrict__ extra,
    const int* __restrict__ deg, const float* __restrict__ deg_emb)
{
    // destination resolved in DEVICE code (correct device addresses)
    float* C;
    if      (MODE == 0) C = g_q;
    else if (MODE == 1) C = g_k;
    else if (MODE == 5) C = g_v;
    else                C = Cparam;

    __shared__ __nv_bfloat16 Ahs[BMT * ALD], Als[BMT * ALD];
    __shared__ __nv_bfloat16 Bhs[16 * BLD], Bls[16 * BLD];
    __shared__ float stage[8 * 256];

    const int tid = threadIdx.x;
    const int m0 = blockIdx.y * BMT, n0 = blockIdx.x * BNT;
    const int warp = tid >> 5, lane = tid & 31;
    const int wm = (warp & 3) * 32, wn = (warp >> 2) * 64;

    wmma::fragment<wmma::accumulator, 16, 16, 16, float> acc[2][4];
#pragma unroll
    for (int mf = 0; mf < 2; mf++)
#pragma unroll
        for (int nf = 0; nf < 4; nf++) wmma::fill_fragment(acc[mf][nf], 0.0f);

    for (int k0 = 0; k0 < K; k0 += 16) {
        // ---- A tile 128x16 ----
#pragma unroll
        for (int i = 0; i < 8; i++) {
            int s = tid + i * 256;
            int m = s >> 4, kk = s & 15;
            float v = loadA<MODE>(m0 + m, k0 + kk, M, K, A, idx, extra);
            __nv_bfloat16 h = __float2bfloat16_rn(v);
            __nv_bfloat16 l = __float2bfloat16_rn(v - __bfloat162float(h));
            Ahs[m * ALD + kk] = h;
            Als[m * ALD + kk] = l;
        }
        // ---- B tile 16x128 (row-major k x n) ----
#pragma unroll
        for (int i = 0; i < 8; i++) {
            int s = tid + i * 256;
            int kk = s >> 7, n = s & 127;
            float v = B[(size_t)(k0 + kk) * NN + n0 + n];
            __nv_bfloat16 h = __float2bfloat16_rn(v);
            __nv_bfloat16 l = __float2bfloat16_rn(v - __bfloat162float(h));
            Bhs[kk * BLD + n] = h;
            Bls[kk * BLD + n] = l;
        }
        __syncthreads();

        wmma::fragment<wmma::matrix_a, 16, 16, 16, __nv_bfloat16, wmma::row_major> ah[2], al[2];
#pragma unroll
        for (int mf = 0; mf < 2; mf++) {
            wmma::load_matrix_sync(ah[mf], Ahs + (wm + mf * 16) * ALD, ALD);
            wmma::load_matrix_sync(al[mf], Als + (wm + mf * 16) * ALD, ALD);
        }
#pragma unroll
        for (int nf = 0; nf < 4; nf++) {
            wmma::fragment<wmma::matrix_b, 16, 16, 16, __nv_bfloat16, wmma::row_major> bh, bl;
            wmma::load_matrix_sync(bh, Bhs + wn + nf * 16, BLD);
            wmma::load_matrix_sync(bl, Bls + wn + nf * 16, BLD);
#pragma unroll
            for (int mf = 0; mf < 2; mf++) {
                wmma::mma_sync(acc[mf][nf], ah[mf], bh, acc[mf][nf]);
                wmma::mma_sync(acc[mf][nf], al[mf], bh, acc[mf][nf]);
                wmma::mma_sync(acc[mf][nf], ah[mf], bl, acc[mf][nf]);
            }
        }
        __syncthreads();
    }

    // ---- epilogue: stage each 16x16 fragment through smem (layout-safe) ----
    float* st = stage + warp * 256;
#pragma unroll
    for (int mf = 0; mf < 2; mf++) {
#pragma unroll
        for (int nf = 0; nf < 4; nf++) {
            wmma::store_matrix_sync(st, acc[mf][nf], 16, wmma::mem_row_major);
            __syncwarp();
#pragma unroll
            for (int e = lane; e < 256; e += 32) {
                int r = e >> 4, c = e & 15;
                int gm = m0 + wm + mf * 16 + r;
                int gn = n0 + wn + nf * 16 + c;
                if (gm < M) {
                    float val = st[e] + bias[gn];
                    if (MODE == 1) {
                        if (gn >= 256) val += deg_emb[(size_t)deg[gm] * 256 + (gn - 256)];
                        C[(size_t)gm * NN + gn] = val;
                    } else if (MODE == 2) {
                        if (gn < 256) g_ab[(size_t)gm * 256 + gn] = val;
                        else          g_vb[(size_t)gm * 256 + (gn - 256)] = val;
                    } else {
                        C[(size_t)gm * NN + gn] = val;
                    }
                }
            }
            __syncwarp();
        }
    }
}

// ---------------- local attention (one block = one edge) --------------------
__global__ void local_att(const int* __restrict__ bond_idx)
{
    int e = blockIdx.x;
    int t = threadIdx.x;  // 0..255 : head = t>>5, dim = t&31
    int src = __ldg(&bond_idx[e]);
    int dst = __ldg(&bond_idx[ELOCAL + e]);
    float qv = g_q[(size_t)dst * 512 + t];
    float kv = g_k[(size_t)src * 512 + t];
    float vv = g_v[(size_t)src * 512 + t];
    float prod = qv * kv;
    if (e < EBOND) {
        prod += g_ab[(size_t)e * 256 + t];
        vv   += g_vb[(size_t)e * 256 + t];
    }
    float s = prod;
#pragma unroll
    for (int o = 16; o; o >>= 1) s += __shfl_xor_sync(0xffffffffu, s, o);
    float es = expf(s * SCALE);
    atomicAdd(&g_lacc[(size_t)dst * 256 + t], es * vv);
    if ((t & 31) == 0) atomicAdd(&g_lsum[dst * HEADS + (t >> 5)], es);
}

// ---------------- global attention (one block = one edge) -------------------
__global__ void global_att(const int* __restrict__ qi, const int* __restrict__ ki,
                           const int* __restrict__ dist, const float* __restrict__ dist_emb)
{
    int e = blockIdx.x;
    int t = threadIdx.x;
    int q = __ldg(&qi[e]);
    int k = __ldg(&ki[e]);
    int dd = __ldg(&dist[e]);
    float prod = g_q[(size_t)q * 512 + 256 + t] * g_k[(size_t)k * 512 + 256 + t]
               + __ldg(&dist_emb[(size_t)dd * 256 + t]);
    if (e < EBOND) prod += g_ab[(size_t)e * 256 + t];
    float s = prod;
#pragma unroll
    for (int o = 16; o; o >>= 1) s += __shfl_xor_sync(0xffffffffu, s, o);
    float es = expf(s * SCALE);
    float vv = g_v[(size_t)k * 512 + 256 + t];
    atomicAdd(&g_gacc[(size_t)q * 256 + t], es * vv);
    if ((t & 31) == 0) atomicAdd(&g_gsum[q * HEADS + (t >> 5)], es);
}

// ---------------- launch -----------------------------------------------------
extern "C" void kernel_launch(void* const* d_in, const int* in_sizes, int n_in,
                              void* d_out, int out_size)
{
    const float* f_node   = (const float*)d_in[0];
    const float* f_bond   = (const float*)d_in[1];
    const int*   deg      = (const int*)d_in[2];
    const int*   dist     = (const int*)d_in[3];
    const int*   bond_idx = (const int*)d_in[4];
    const int*   query_ix = (const int*)d_in[5];
    const int*   key_ix   = (const int*)d_in[6];
    // d_in[7] attention_bond_idx == arange(E_BOND) (positional identity)
    const float* deg_emb  = (const float*)d_in[8];
    const float* dist_emb = (const float*)d_in[9];
    const float* Wq_w = (const float*)d_in[10]; const float* Wq_b = (const float*)d_in[11];
    const float* Wk_w = (const float*)d_in[12]; const float* Wk_b = (const float*)d_in[13];
    const float* Wv_w = (const float*)d_in[14]; const float* Wv_b = (const float*)d_in[15];
    const float* out_w = (const float*)d_in[16]; const float* out_b = (const float*)d_in[17];
    const float* be_w = (const float*)d_in[18]; const float* be_b = (const float*)d_in[19];
    const float* bu_w = (const float*)d_in[20]; const float* bu_b = (const float*)d_in[21];

    float* out      = (float*)d_out;                      // (NNODE, 256)
    float* bond_out = out + (size_t)NNODE * 256;          // (EBOND, 256)

    zero_kernel<<<(NNODE * 256 + 255) / 256, 256>>>();

    dim3 gN512(512 / BNT, (NNODE + BMT - 1) / BMT);
    dim3 gE512(512 / BNT, (EBOND + BMT - 1) / BMT);
    dim3 gN256(256 / BNT, (NNODE + BMT - 1) / BMT);
    dim3 gE256(256 / BNT, (EBOND + BMT - 1) / BMT);

    // q/k/v: M=NNODE, K=256, NN=512 (destinations are device symbols, chosen
    // inside the kernel by MODE — never passed from host!)
    tgemm<0><<<gN512, 256>>>(NNODE, 256, 512, f_node, Wq_w, Wq_b, nullptr,
                             nullptr, nullptr, nullptr, nullptr);
    tgemm<1><<<gN512, 256>>>(NNODE, 256, 512, f_node, Wk_w, Wk_b, nullptr,
                             nullptr, nullptr, deg, deg_emb);
    tgemm<5><<<gN512, 256>>>(NNODE, 256, 512, f_node, Wv_w, Wv_b, nullptr,
                             nullptr, nullptr, nullptr, nullptr);

    // bond embedding: M=EBOND, K=256, NN=512 -> g_ab / g_vb (device-internal)
    tgemm<2><<<gE512, 256>>>(EBOND, 256, 512, f_bond, be_w, be_b, nullptr,
                             nullptr, nullptr, nullptr, nullptr);

    local_att<<<ELOCAL, 256>>>(bond_idx);
    global_att<<<EGLOBAL, 256>>>(query_ix, key_ix, dist, dist_emb);

    // out = [lacc/lsum | gacc/gsum] @ out_w + out_b : M=NNODE, K=512, NN=256
    tgemm<3><<<gN256, 256>>>(NNODE, 512, 256, nullptr, out_w, out_b, out,
                             nullptr, nullptr, nullptr, nullptr);

    // bond_out = [f_bond | out[src]] @ bu_w + bu_b : M=EBOND, K=512, NN=256
    tgemm<4><<<gE256, 256>>>(EBOND, 512, 256, f_bond, bu_w, bu_b, bond_out,
                             bond_idx, out, nullptr, nullptr);
}

// round 11
// speedup vs baseline: 1.7045x; 1.5690x over previous
#include <cuda_runtime.h>
#include <cuda_bf16.h>
#include <mma.h>
#include <math.h>

using namespace nvcuda;

#define HEADS 8
#define DHEAD 32
#define DMODEL 256
#define NNODE 20000
#define ELOCAL 80000
#define EBOND 60000
#define EGLOBAL 400000
#define SCALE 0.17677669529663687f  // 1/sqrt(32)

// ---------------- scratch (device globals; no allocation allowed) ----------
// NOTE: never pass these as kernel arguments from HOST code — the host sees
// the shadow-object address and GB300 ATS dereferences it silently (R4-R6 bug).
__device__ float g_q[(size_t)NNODE * 512];
__device__ float g_k[(size_t)NNODE * 512];   // global half already includes deg_emb
__device__ float g_v[(size_t)NNODE * 512];
__device__ float g_ab[(size_t)EBOND * 256];  // attention_bond
__device__ float g_vb[(size_t)EBOND * 256];  // value_bond
__device__ float g_lacc[(size_t)NNODE * 256];
__device__ float g_gacc[(size_t)NNODE * 256];
__device__ float g_lsum[(size_t)NNODE * HEADS];
__device__ float g_gsum[(size_t)NNODE * HEADS];

// ---------------- zero accumulators ----------------------------------------
__global__ void zero_kernel() {
    int i = blockIdx.x * blockDim.x + threadIdx.x;
    if (i < NNODE * 256) { g_lacc[i] = 0.f; g_gacc[i] = 0.f; }
    if (i < NNODE * HEADS) { g_lsum[i] = 0.f; g_gsum[i] = 0.f; }
}

// ---------------- helpers ----------------------------------------------------
__device__ __forceinline__ unsigned pack_bf16x2(float a, float b) {
    __nv_bfloat162 t = __float22bfloat162_rn(make_float2(a, b));
    return *reinterpret_cast<unsigned*>(&t);
}
__device__ __forceinline__ float bf16_hi(float x) {
    return __bfloat162float(__float2bfloat16_rn(x));
}

// ---------------- wmma split-bf16 GEMM ---------------------------------------
// Block tile 128x128x32, 256 threads = 8 warps (4m x 2n), warp tile 32x64.
// 3-term bf16 split: acc += Ahi*Bhi + Alo*Bhi + Ahi*Blo (~1e-5 relative).
// Register-staged prefetch: next tile's LDG.128s issue before the MMA phase.
//
// MODE 0: C -> g_q   MODE 1: C -> g_k (+deg_emb on cols>=256)   MODE 5: C -> g_v
// MODE 2: split store -> g_ab / g_vb
// MODE 3: A = normalized [lacc|gacc] (K=512), C = param
// MODE 4: A = [f_bond | extra[idx[row]]] (K=512), C = param
#define BMT 128
#define BNT 128
#define BKT 32
#define ALD 40    // A smem leading dim (bf16): 80B, multiple of 16B
#define BLD 136   // B smem leading dim (bf16): 272B, multiple of 16B

template<int MODE>
__device__ __forceinline__ float4 loadA4(int gm, int gk, int M, int K,
                                         const float* __restrict__ A,
                                         const int* __restrict__ idx,
                                         const float* __restrict__ extra)
{
    if (gm >= M) return make_float4(0.f, 0.f, 0.f, 0.f);
    if (MODE == 3) {
        float4 v; float su;
        if (gk < 256) {
            su = g_lsum[gm * HEADS + (gk >> 5)];
            v = *reinterpret_cast<const float4*>(&g_lacc[(size_t)gm * 256 + gk]);
        } else {
            int jj = gk - 256;
            su = g_gsum[gm * HEADS + (jj >> 5)];
            v = *reinterpret_cast<const float4*>(&g_gacc[(size_t)gm * 256 + jj]);
        }
        float inv = (su > 0.f) ? 1.f / su : 0.f;
        v.x *= inv; v.y *= inv; v.z *= inv; v.w *= inv;
        return v;
    } else if (MODE == 4) {
        if (gk < 256) return *reinterpret_cast<const float4*>(&A[(size_t)gm * 256 + gk]);
        return *reinterpret_cast<const float4*>(&extra[(size_t)idx[gm] * 256 + (gk - 256)]);
    } else {
        return *reinterpret_cast<const float4*>(&A[(size_t)gm * K + gk]);
    }
}

template<int MODE>
__global__ void __launch_bounds__(256) tgemm(
    int M, int K, int NN,
    const float* __restrict__ A, const float* __restrict__ B,
    const float* __restrict__ bias, float* __restrict__ Cparam,
    const int* __restrict__ idx, const float* __restrict__ extra,
    const int* __restrict__ deg, const float* __restrict__ deg_emb)
{
    float* C;
    if      (MODE == 0) C = g_q;
    else if (MODE == 1) C = g_k;
    else if (MODE == 5) C = g_v;
    else                C = Cparam;

    __shared__ __nv_bfloat16 Ahs[BMT * ALD], Als[BMT * ALD];
    __shared__ __nv_bfloat16 Bhs[BKT * BLD], Bls[BKT * BLD];
    __shared__ float stage[8 * 256];

    const int tid = threadIdx.x;
    const int m0 = blockIdx.y * BMT, n0 = blockIdx.x * BNT;
    const int warp = tid >> 5, lane = tid & 31;
    const int wm = (warp & 3) * 32, wn = (warp >> 2) * 64;

    // A: thread covers row am, k-range [ak0, ak0+16)  (128 x 32 tile)
    const int am = tid >> 1, ak0 = (tid & 1) * 16;
    // B: thread covers row bk, n-range [bn0, bn0+16)  (32 x 128 tile)
    const int bk = tid >> 3, bn0 = (tid & 7) * 16;

    wmma::fragment<wmma::accumulator, 16, 16, 16, float> acc[2][4];
#pragma unroll
    for (int mf = 0; mf < 2; mf++)
#pragma unroll
        for (int nf = 0; nf < 4; nf++) wmma::fill_fragment(acc[mf][nf], 0.0f);

    float4 pa[4], pb[4];
#pragma unroll
    for (int i = 0; i < 4; i++) {
        pa[i] = loadA4<MODE>(m0 + am, ak0 + 4 * i, M, K, A, idx, extra);
        pb[i] = *reinterpret_cast<const float4*>(&B[(size_t)bk * NN + n0 + bn0 + 4 * i]);
    }

    for (int k0 = 0; k0 < K; k0 += BKT) {
        // ---- convert + store the prefetched tile ----
#pragma unroll
        for (int i = 0; i < 4; i++) {
            float x0 = pa[i].x, x1 = pa[i].y, x2 = pa[i].z, x3 = pa[i].w;
            float h0 = bf16_hi(x0), h1 = bf16_hi(x1), h2 = bf16_hi(x2), h3 = bf16_hi(x3);
            unsigned* dh = reinterpret_cast<unsigned*>(&Ahs[am * ALD + ak0 + 4 * i]);
            unsigned* dl = reinterpret_cast<unsigned*>(&Als[am * ALD + ak0 + 4 * i]);
            dh[0] = pack_bf16x2(x0, x1);            dh[1] = pack_bf16x2(x2, x3);
            dl[0] = pack_bf16x2(x0 - h0, x1 - h1);  dl[1] = pack_bf16x2(x2 - h2, x3 - h3);

            float y0 = pb[i].x, y1 = pb[i].y, y2 = pb[i].z, y3 = pb[i].w;
            float g0 = bf16_hi(y0), g1 = bf16_hi(y1), g2 = bf16_hi(y2), g3 = bf16_hi(y3);
            unsigned* eh = reinterpret_cast<unsigned*>(&Bhs[bk * BLD + bn0 + 4 * i]);
            unsigned* el = reinterpret_cast<unsigned*>(&Bls[bk * BLD + bn0 + 4 * i]);
            eh[0] = pack_bf16x2(y0, y1);            eh[1] = pack_bf16x2(y2, y3);
            el[0] = pack_bf16x2(y0 - g0, y1 - g1);  el[1] = pack_bf16x2(y2 - g2, y3 - g3);
        }
        __syncthreads();

        // ---- prefetch next tile (LDGs overlap the MMA phase below) ----
        if (k0 + BKT < K) {
#pragma unroll
            for (int i = 0; i < 4; i++) {
                pa[i] = loadA4<MODE>(m0 + am, k0 + BKT + ak0 + 4 * i, M, K, A, idx, extra);
                pb[i] = *reinterpret_cast<const float4*>(
                            &B[(size_t)(k0 + BKT + bk) * NN + n0 + bn0 + 4 * i]);
            }
        }

        // ---- MMA phase: 2 k16 steps ----
#pragma unroll
        for (int ks = 0; ks < BKT; ks += 16) {
            wmma::fragment<wmma::matrix_a, 16, 16, 16, __nv_bfloat16, wmma::row_major> ah[2], al[2];
#pragma unroll
            for (int mf = 0; mf < 2; mf++) {
                wmma::load_matrix_sync(ah[mf], Ahs + (wm + mf * 16) * ALD + ks, ALD);
                wmma::load_matrix_sync(al[mf], Als + (wm + mf * 16) * ALD + ks, ALD);
            }
#pragma unroll
            for (int nf = 0; nf < 4; nf++) {
                wmma::fragment<wmma::matrix_b, 16, 16, 16, __nv_bfloat16, wmma::row_major> bh, bl;
                wmma::load_matrix_sync(bh, Bhs + ks * BLD + wn + nf * 16, BLD);
                wmma::load_matrix_sync(bl, Bls + ks * BLD + wn + nf * 16, BLD);
#pragma unroll
                for (int mf = 0; mf < 2; mf++) {
                    wmma::mma_sync(acc[mf][nf], ah[mf], bh, acc[mf][nf]);
                    wmma::mma_sync(acc[mf][nf], al[mf], bh, acc[mf][nf]);
                    wmma::mma_sync(acc[mf][nf], ah[mf], bl, acc[mf][nf]);
                }
            }
        }
        __syncthreads();
    }

    // ---- epilogue: stage each 16x16 fragment through smem (layout-safe) ----
    float* st = stage + warp * 256;
#pragma unroll
    for (int mf = 0; mf < 2; mf++) {
#pragma unroll
        for (int nf = 0; nf < 4; nf++) {
            wmma::store_matrix_sync(st, acc[mf][nf], 16, wmma::mem_row_major);
            __syncwarp();
#pragma unroll
            for (int e = lane; e < 256; e += 32) {
                int r = e >> 4, c = e & 15;
                int gm = m0 + wm + mf * 16 + r;
                int gn = n0 + wn + nf * 16 + c;
                if (gm < M) {
                    float val = st[e] + bias[gn];
                    if (MODE == 1) {
                        if (gn >= 256) val += deg_emb[(size_t)deg[gm] * 256 + (gn - 256)];
                        C[(size_t)gm * NN + gn] = val;
                    } else if (MODE == 2) {
                        if (gn < 256) g_ab[(size_t)gm * 256 + gn] = val;
                        else          g_vb[(size_t)gm * 256 + (gn - 256)] = val;
                    } else {
                        C[(size_t)gm * NN + gn] = val;
                    }
                }
            }
            __syncwarp();
        }
    }
}

// ---------------- local attention (grid-stride, 256 thr = 1 edge) ------------
__global__ void local_att(const int* __restrict__ bond_idx)
{
    int t = threadIdx.x;  // head = t>>5, dim = t&31
    for (int e = blockIdx.x; e < ELOCAL; e += gridDim.x) {
        int src = __ldg(&bond_idx[e]);
        int dst = __ldg(&bond_idx[ELOCAL + e]);
        float qv = g_q[(size_t)dst * 512 + t];
        float kv = g_k[(size_t)src * 512 + t];
        float vv = g_v[(size_t)src * 512 + t];
        float prod = qv * kv;
        if (e < EBOND) {
            prod += g_ab[(size_t)e * 256 + t];
            vv   += g_vb[(size_t)e * 256 + t];
        }
        float s = prod;
#pragma unroll
        for (int o = 16; o; o >>= 1) s += __shfl_xor_sync(0xffffffffu, s, o);
        float es = __expf(s * SCALE);
        atomicAdd(&g_lacc[(size_t)dst * 256 + t], es * vv);
        if ((t & 31) == 0) atomicAdd(&g_lsum[dst * HEADS + (t >> 5)], es);
    }
}

// ---------------- global attention (grid-stride, 256 thr = 1 edge) -----------
__global__ void global_att(const int* __restrict__ qi, const int* __restrict__ ki,
                           const int* __restrict__ dist, const float* __restrict__ dist_emb)
{
    int t = threadIdx.x;
    for (int e = blockIdx.x; e < EGLOBAL; e += gridDim.x) {
        int q = __ldg(&qi[e]);
        int k = __ldg(&ki[e]);
        int dd = __ldg(&dist[e]);
        float prod = g_q[(size_t)q * 512 + 256 + t] * g_k[(size_t)k * 512 + 256 + t]
                   + __ldg(&dist_emb[(size_t)dd * 256 + t]);
        if (e < EBOND) prod += g_ab[(size_t)e * 256 + t];
        float s = prod;
#pragma unroll
        for (int o = 16; o; o >>= 1) s += __shfl_xor_sync(0xffffffffu, s, o);
        float es = __expf(s * SCALE);
        float vv = g_v[(size_t)k * 512 + 256 + t];
        atomicAdd(&g_gacc[(size_t)q * 256 + t], es * vv);
        if ((t & 31) == 0) atomicAdd(&g_gsum[q * HEADS + (t >> 5)], es);
    }
}

// ---------------- launch -----------------------------------------------------
extern "C" void kernel_launch(void* const* d_in, const int* in_sizes, int n_in,
                              void* d_out, int out_size)
{
    const float* f_node   = (const float*)d_in[0];
    const float* f_bond   = (const float*)d_in[1];
    const int*   deg      = (const int*)d_in[2];
    const int*   dist     = (const int*)d_in[3];
    const int*   bond_idx = (const int*)d_in[4];
    const int*   query_ix = (const int*)d_in[5];
    const int*   key_ix   = (const int*)d_in[6];
    // d_in[7] attention_bond_idx == arange(E_BOND) (positional identity)
    const float* deg_emb  = (const float*)d_in[8];
    const float* dist_emb = (const float*)d_in[9];
    const float* Wq_w = (const float*)d_in[10]; const float* Wq_b = (const float*)d_in[11];
    const float* Wk_w = (const float*)d_in[12]; const float* Wk_b = (const float*)d_in[13];
    const float* Wv_w = (const float*)d_in[14]; const float* Wv_b = (const float*)d_in[15];
    const float* out_w = (const float*)d_in[16]; const float* out_b = (const float*)d_in[17];
    const float* be_w = (const float*)d_in[18]; const float* be_b = (const float*)d_in[19];
    const float* bu_w = (const float*)d_in[20]; const float* bu_b = (const float*)d_in[21];

    float* out      = (float*)d_out;                      // (NNODE, 256)
    float* bond_out = out + (size_t)NNODE * 256;          // (EBOND, 256)

    zero_kernel<<<(NNODE * 256 + 255) / 256, 256>>>();

    dim3 gN512(512 / BNT, (NNODE + BMT - 1) / BMT);
    dim3 gE512(512 / BNT, (EBOND + BMT - 1) / BMT);
    dim3 gN256(256 / BNT, (NNODE + BMT - 1) / BMT);
    dim3 gE256(256 / BNT, (EBOND + BMT - 1) / BMT);

    // q/k/v: M=NNODE, K=256, NN=512 (destinations resolved device-side by MODE)
    tgemm<0><<<gN512, 256>>>(NNODE, 256, 512, f_node, Wq_w, Wq_b, nullptr,
                             nullptr, nullptr, nullptr, nullptr);
    tgemm<1><<<gN512, 256>>>(NNODE, 256, 512, f_node, Wk_w, Wk_b, nullptr,
                             nullptr, nullptr, deg, deg_emb);
    tgemm<5><<<gN512, 256>>>(NNODE, 256, 512, f_node, Wv_w, Wv_b, nullptr,
                             nullptr, nullptr, nullptr, nullptr);

    // bond embedding: M=EBOND, K=256, NN=512 -> g_ab / g_vb (device-internal)
    tgemm<2><<<gE512, 256>>>(EBOND, 256, 512, f_bond, be_w, be_b, nullptr,
                             nullptr, nullptr, nullptr, nullptr);

    local_att<<<4096, 256>>>(bond_idx);
    global_att<<<8192, 256>>>(query_ix, key_ix, dist, dist_emb);

    // out = [lacc/lsum | gacc/gsum] @ out_w + out_b : M=NNODE, K=512, NN=256
    tgemm<3><<<gN256, 256>>>(NNODE, 512, 256, nullptr, out_w, out_b, out,
                             nullptr, nullptr, nullptr, nullptr);

    // bond_out = [f_bond | out[src]] @ bu_w + bu_b : M=EBOND, K=512, NN=256
    tgemm<4><<<gE256, 256>>>(EBOND, 512, 256, f_bond, bu_w, bu_b, bond_out,
                             bond_idx, out, nullptr, nullptr);
}

// round 12
// speedup vs baseline: 1.8572x; 1.0895x over previous
#include <cuda_runtime.h>
#include <cuda_bf16.h>
#include <mma.h>
#include <math.h>

using namespace nvcuda;

#define HEADS 8
#define DHEAD 32
#define DMODEL 256
#define NNODE 20000
#define ELOCAL 80000
#define EBOND 60000
#define EGLOBAL 400000
#define SCALE 0.17677669529663687f  // 1/sqrt(32)

// ---------------- scratch (device globals; no allocation allowed) ----------
// NOTE: never pass these as kernel arguments from HOST code — the host sees
// the shadow-object address and GB300 ATS dereferences it silently (R4-R6 bug).
__device__ float g_q[(size_t)NNODE * 512];
__device__ float g_k[(size_t)NNODE * 512];   // global half already includes deg_emb
__device__ float g_v[(size_t)NNODE * 512];
__device__ float g_ab[(size_t)EBOND * 256];  // attention_bond
__device__ float g_vb[(size_t)EBOND * 256];  // value_bond
__device__ float g_lacc[(size_t)NNODE * 256];
__device__ float g_gacc[(size_t)NNODE * 256];
__device__ float g_lsum[(size_t)NNODE * HEADS];
__device__ float g_gsum[(size_t)NNODE * HEADS];

// ---------------- zero accumulators ----------------------------------------
__global__ void zero_kernel() {
    int i = blockIdx.x * blockDim.x + threadIdx.x;
    if (i < NNODE * 256) { g_lacc[i] = 0.f; g_gacc[i] = 0.f; }
    if (i < NNODE * HEADS) { g_lsum[i] = 0.f; g_gsum[i] = 0.f; }
}

// ---------------- helpers ----------------------------------------------------
__device__ __forceinline__ unsigned pack_bf16x2(float a, float b) {
    __nv_bfloat162 t = __float22bfloat162_rn(make_float2(a, b));
    return *reinterpret_cast<unsigned*>(&t);
}
__device__ __forceinline__ float bf16_hi(float x) {
    return __bfloat162float(__float2bfloat16_rn(x));
}

// ---------------- wmma split-bf16 GEMM ---------------------------------------
// Block tile 128x64x32, 256 threads = 8 warps (4m x 2n), warp tile 32x32.
// 2 CTAs/SM (launch_bounds) -> 16 warps/SM hides barrier + smem latency.
// 3-term bf16 split: acc += Ahi*Bhi + Alo*Bhi + Ahi*Blo (~1e-5 relative).
//
// MODE 0: C -> g_q   MODE 1: C -> g_k (+deg_emb on cols>=256)   MODE 5: C -> g_v
// MODE 2: split store -> g_ab / g_vb
// MODE 3: A = normalized [lacc|gacc] (K=512), C = param
// MODE 4: A = [f_bond | extra[idx[row]]] (K=512), C = param
#define BMT 128
#define BNT 64
#define BKT 32
#define ALD 40    // A smem leading dim (bf16): 80B, multiple of 16B
#define BLD 72    // B smem leading dim (bf16): 144B, multiple of 16B

template<int MODE>
__device__ __forceinline__ float4 loadA4(int gm, int gk, int M, int K,
                                         const float* __restrict__ A,
                                         const int* __restrict__ idx,
                                         const float* __restrict__ extra)
{
    if (gm >= M) return make_float4(0.f, 0.f, 0.f, 0.f);
    if (MODE == 3) {
        float4 v; float su;
        if (gk < 256) {
            su = g_lsum[gm * HEADS + (gk >> 5)];
            v = *reinterpret_cast<const float4*>(&g_lacc[(size_t)gm * 256 + gk]);
        } else {
            int jj = gk - 256;
            su = g_gsum[gm * HEADS + (jj >> 5)];
            v = *reinterpret_cast<const float4*>(&g_gacc[(size_t)gm * 256 + jj]);
        }
        float inv = (su > 0.f) ? 1.f / su : 0.f;
        v.x *= inv; v.y *= inv; v.z *= inv; v.w *= inv;
        return v;
    } else if (MODE == 4) {
        if (gk < 256) return *reinterpret_cast<const float4*>(&A[(size_t)gm * 256 + gk]);
        return *reinterpret_cast<const float4*>(&extra[(size_t)idx[gm] * 256 + (gk - 256)]);
    } else {
        return *reinterpret_cast<const float4*>(&A[(size_t)gm * K + gk]);
    }
}

template<int MODE>
__global__ void __launch_bounds__(256, 2) tgemm(
    int M, int K, int NN,
    const float* __restrict__ A, const float* __restrict__ B,
    const float* __restrict__ bias, float* __restrict__ Cparam,
    const int* __restrict__ idx, const float* __restrict__ extra,
    const int* __restrict__ deg, const float* __restrict__ deg_emb)
{
    float* C;
    if      (MODE == 0) C = g_q;
    else if (MODE == 1) C = g_k;
    else if (MODE == 5) C = g_v;
    else                C = Cparam;

    __shared__ __nv_bfloat16 Ahs[BMT * ALD], Als[BMT * ALD];
    __shared__ __nv_bfloat16 Bhs[BKT * BLD], Bls[BKT * BLD];
    __shared__ float stage[8 * 256];

    const int tid = threadIdx.x;
    const int m0 = blockIdx.y * BMT, n0 = blockIdx.x * BNT;
    const int warp = tid >> 5, lane = tid & 31;
    const int wm = (warp & 3) * 32, wn = (warp >> 2) * 32;

    // A: thread covers row am, k-range [ak0, ak0+16)  (128 x 32 tile, 4 float4)
    const int am = tid >> 1, ak0 = (tid & 1) * 16;
    // B: thread covers row bk, n-range [bn0, bn0+8)   (32 x 64 tile, 2 float4)
    const int bk = tid >> 3, bn0 = (tid & 7) * 8;

    wmma::fragment<wmma::accumulator, 16, 16, 16, float> acc[2][2];
#pragma unroll
    for (int mf = 0; mf < 2; mf++)
#pragma unroll
        for (int nf = 0; nf < 2; nf++) wmma::fill_fragment(acc[mf][nf], 0.0f);

    float4 pa[4], pb[2];
#pragma unroll
    for (int i = 0; i < 4; i++)
        pa[i] = loadA4<MODE>(m0 + am, ak0 + 4 * i, M, K, A, idx, extra);
#pragma unroll
    for (int i = 0; i < 2; i++)
        pb[i] = *reinterpret_cast<const float4*>(&B[(size_t)bk * NN + n0 + bn0 + 4 * i]);

    for (int k0 = 0; k0 < K; k0 += BKT) {
        // ---- convert + store the prefetched tile ----
#pragma unroll
        for (int i = 0; i < 4; i++) {
            float x0 = pa[i].x, x1 = pa[i].y, x2 = pa[i].z, x3 = pa[i].w;
            float h0 = bf16_hi(x0), h1 = bf16_hi(x1), h2 = bf16_hi(x2), h3 = bf16_hi(x3);
            unsigned* dh = reinterpret_cast<unsigned*>(&Ahs[am * ALD + ak0 + 4 * i]);
            unsigned* dl = reinterpret_cast<unsigned*>(&Als[am * ALD + ak0 + 4 * i]);
            dh[0] = pack_bf16x2(x0, x1);            dh[1] = pack_bf16x2(x2, x3);
            dl[0] = pack_bf16x2(x0 - h0, x1 - h1);  dl[1] = pack_bf16x2(x2 - h2, x3 - h3);
        }
#pragma unroll
        for (int i = 0; i < 2; i++) {
            float y0 = pb[i].x, y1 = pb[i].y, y2 = pb[i].z, y3 = pb[i].w;
            float g0 = bf16_hi(y0), g1 = bf16_hi(y1), g2 = bf16_hi(y2), g3 = bf16_hi(y3);
            unsigned* eh = reinterpret_cast<unsigned*>(&Bhs[bk * BLD + bn0 + 4 * i]);
            unsigned* el = reinterpret_cast<unsigned*>(&Bls[bk * BLD + bn0 + 4 * i]);
            eh[0] = pack_bf16x2(y0, y1);            eh[1] = pack_bf16x2(y2, y3);
            el[0] = pack_bf16x2(y0 - g0, y1 - g1);  el[1] = pack_bf16x2(y2 - g2, y3 - g3);
        }
        __syncthreads();

        // ---- prefetch next tile (LDGs overlap the MMA phase below) ----
        if (k0 + BKT < K) {
#pragma unroll
            for (int i = 0; i < 4; i++)
                pa[i] = loadA4<MODE>(m0 + am, k0 + BKT + ak0 + 4 * i, M, K, A, idx, extra);
#pragma unroll
            for (int i = 0; i < 2; i++)
                pb[i] = *reinterpret_cast<const float4*>(
                            &B[(size_t)(k0 + BKT + bk) * NN + n0 + bn0 + 4 * i]);
        }

        // ---- MMA phase: 2 k16 steps ----
#pragma unroll
        for (int ks = 0; ks < BKT; ks += 16) {
            wmma::fragment<wmma::matrix_a, 16, 16, 16, __nv_bfloat16, wmma::row_major> ah[2], al[2];
#pragma unroll
            for (int mf = 0; mf < 2; mf++) {
                wmma::load_matrix_sync(ah[mf], Ahs + (wm + mf * 16) * ALD + ks, ALD);
                wmma::load_matrix_sync(al[mf], Als + (wm + mf * 16) * ALD + ks, ALD);
            }
#pragma unroll
            for (int nf = 0; nf < 2; nf++) {
                wmma::fragment<wmma::matrix_b, 16, 16, 16, __nv_bfloat16, wmma::row_major> bh, bl;
                wmma::load_matrix_sync(bh, Bhs + ks * BLD + wn + nf * 16, BLD);
                wmma::load_matrix_sync(bl, Bls + ks * BLD + wn + nf * 16, BLD);
#pragma unroll
                for (int mf = 0; mf < 2; mf++) {
                    wmma::mma_sync(acc[mf][nf], ah[mf], bh, acc[mf][nf]);
                    wmma::mma_sync(acc[mf][nf], al[mf], bh, acc[mf][nf]);
                    wmma::mma_sync(acc[mf][nf], ah[mf], bl, acc[mf][nf]);
                }
            }
        }
        __syncthreads();
    }

    // ---- epilogue: stage each 16x16 fragment through smem (layout-safe) ----
    float* st = stage + warp * 256;
#pragma unroll
    for (int mf = 0; mf < 2; mf++) {
#pragma unroll
        for (int nf = 0; nf < 2; nf++) {
            wmma::store_matrix_sync(st, acc[mf][nf], 16, wmma::mem_row_major);
            __syncwarp();
#pragma unroll
            for (int e = lane; e < 256; e += 32) {
                int r = e >> 4, c = e & 15;
                int gm = m0 + wm + mf * 16 + r;
                int gn = n0 + wn + nf * 16 + c;
                if (gm < M) {
                    float val = st[e] + bias[gn];
                    if (MODE == 1) {
                        if (gn >= 256) val += deg_emb[(size_t)deg[gm] * 256 + (gn - 256)];
                        C[(size_t)gm * NN + gn] = val;
                    } else if (MODE == 2) {
                        if (gn < 256) g_ab[(size_t)gm * 256 + gn] = val;
                        else          g_vb[(size_t)gm * 256 + (gn - 256)] = val;
                    } else {
                        C[(size_t)gm * NN + gn] = val;
                    }
                }
            }
            __syncwarp();
        }
    }
}

// ---------------- local attention (grid-stride, 256 thr = 1 edge) ------------
__global__ void local_att(const int* __restrict__ bond_idx)
{
    int t = threadIdx.x;  // head = t>>5, dim = t&31
    for (int e = blockIdx.x; e < ELOCAL; e += gridDim.x) {
        int src = __ldg(&bond_idx[e]);
        int dst = __ldg(&bond_idx[ELOCAL + e]);
        float qv = g_q[(size_t)dst * 512 + t];
        float kv = g_k[(size_t)src * 512 + t];
        float vv = g_v[(size_t)src * 512 + t];
        float prod = qv * kv;
        if (e < EBOND) {
            prod += g_ab[(size_t)e * 256 + t];
            vv   += g_vb[(size_t)e * 256 + t];
        }
        float s = prod;
#pragma unroll
        for (int o = 16; o; o >>= 1) s += __shfl_xor_sync(0xffffffffu, s, o);
        float es = __expf(s * SCALE);
        atomicAdd(&g_lacc[(size_t)dst * 256 + t], es * vv);
        if ((t & 31) == 0) atomicAdd(&g_lsum[dst * HEADS + (t >> 5)], es);
    }
}

// ---------------- global attention (grid-stride, 256 thr = 1 edge) -----------
__global__ void global_att(const int* __restrict__ qi, const int* __restrict__ ki,
                           const int* __restrict__ dist, const float* __restrict__ dist_emb)
{
    int t = threadIdx.x;
    for (int e = blockIdx.x; e < EGLOBAL; e += gridDim.x) {
        int q = __ldg(&qi[e]);
        int k = __ldg(&ki[e]);
        int dd = __ldg(&dist[e]);
        float prod = g_q[(size_t)q * 512 + 256 + t] * g_k[(size_t)k * 512 + 256 + t]
                   + __ldg(&dist_emb[(size_t)dd * 256 + t]);
        if (e < EBOND) prod += g_ab[(size_t)e * 256 + t];
        float s = prod;
#pragma unroll
        for (int o = 16; o; o >>= 1) s += __shfl_xor_sync(0xffffffffu, s, o);
        float es = __expf(s * SCALE);
        float vv = g_v[(size_t)k * 512 + 256 + t];
        atomicAdd(&g_gacc[(size_t)q * 256 + t], es * vv);
        if ((t & 31) == 0) atomicAdd(&g_gsum[q * HEADS + (t >> 5)], es);
    }
}

// ---------------- launch -----------------------------------------------------
extern "C" void kernel_launch(void* const* d_in, const int* in_sizes, int n_in,
                              void* d_out, int out_size)
{
    const float* f_node   = (const float*)d_in[0];
    const float* f_bond   = (const float*)d_in[1];
    const int*   deg      = (const int*)d_in[2];
    const int*   dist     = (const int*)d_in[3];
    const int*   bond_idx = (const int*)d_in[4];
    const int*   query_ix = (const int*)d_in[5];
    const int*   key_ix   = (const int*)d_in[6];
    // d_in[7] attention_bond_idx == arange(E_BOND) (positional identity)
    const float* deg_emb  = (const float*)d_in[8];
    const float* dist_emb = (const float*)d_in[9];
    const float* Wq_w = (const float*)d_in[10]; const float* Wq_b = (const float*)d_in[11];
    const float* Wk_w = (const float*)d_in[12]; const float* Wk_b = (const float*)d_in[13];
    const float* Wv_w = (const float*)d_in[14]; const float* Wv_b = (const float*)d_in[15];
    const float* out_w = (const float*)d_in[16]; const float* out_b = (const float*)d_in[17];
    const float* be_w = (const float*)d_in[18]; const float* be_b = (const float*)d_in[19];
    const float* bu_w = (const float*)d_in[20]; const float* bu_b = (const float*)d_in[21];

    float* out      = (float*)d_out;                      // (NNODE, 256)
    float* bond_out = out + (size_t)NNODE * 256;          // (EBOND, 256)

    zero_kernel<<<(NNODE * 256 + 255) / 256, 256>>>();

    dim3 gN512(512 / BNT, (NNODE + BMT - 1) / BMT);
    dim3 gE512(512 / BNT, (EBOND + BMT - 1) / BMT);
    dim3 gN256(256 / BNT, (NNODE + BMT - 1) / BMT);
    dim3 gE256(256 / BNT, (EBOND + BMT - 1) / BMT);

    // q/k/v: M=NNODE, K=256, NN=512 (destinations resolved device-side by MODE)
    tgemm<0><<<gN512, 256>>>(NNODE, 256, 512, f_node, Wq_w, Wq_b, nullptr,
                             nullptr, nullptr, nullptr, nullptr);
    tgemm<1><<<gN512, 256>>>(NNODE, 256, 512, f_node, Wk_w, Wk_b, nullptr,
                             nullptr, nullptr, deg, deg_emb);
    tgemm<5><<<gN512, 256>>>(NNODE, 256, 512, f_node, Wv_w, Wv_b, nullptr,
                             nullptr, nullptr, nullptr, nullptr);

    // bond embedding: M=EBOND, K=256, NN=512 -> g_ab / g_vb (device-internal)
    tgemm<2><<<gE512, 256>>>(EBOND, 256, 512, f_bond, be_w, be_b, nullptr,
                             nullptr, nullptr, nullptr, nullptr);

    local_att<<<4096, 256>>>(bond_idx);
    global_att<<<8192, 256>>>(query_ix, key_ix, dist, dist_emb);

    // out = [lacc/lsum | gacc/gsum] @ out_w + out_b : M=NNODE, K=512, NN=256
    tgemm<3><<<gN256, 256>>>(NNODE, 512, 256, nullptr, out_w, out_b, out,
                             nullptr, nullptr, nullptr, nullptr);

    // bond_out = [f_bond | out[src]] @ bu_w + bu_b : M=EBOND, K=512, NN=256
    tgemm<4><<<gE256, 256>>>(EBOND, 512, 256, f_bond, bu_w, bu_b, bond_out,
                             bond_idx, out, nullptr, nullptr);
}

// round 13
// speedup vs baseline: 2.0635x; 1.1111x over previous
#include <cuda_runtime.h>
#include <cuda_bf16.h>
#include <math.h>

#define HEADS 8
#define DHEAD 32
#define DMODEL 256
#define NNODE 20000
#define ELOCAL 80000
#define EBOND 60000
#define EGLOBAL 400000
#define SCALE 0.17677669529663687f  // 1/sqrt(32)

// ---------------- scratch (device globals; no allocation allowed) ----------
// NOTE: never pass these as kernel arguments from HOST code — the host sees
// the shadow-object address and GB300 ATS dereferences it silently (R4-R6 bug).
__device__ float g_q[(size_t)NNODE * 512];
__device__ float g_k[(size_t)NNODE * 512];   // global half already includes deg_emb
__device__ float g_v[(size_t)NNODE * 512];
__device__ float g_ab[(size_t)EBOND * 256];  // attention_bond
__device__ float g_vb[(size_t)EBOND * 256];  // value_bond
__device__ float g_lacc[(size_t)NNODE * 256];
__device__ float g_gacc[(size_t)NNODE * 256];
__device__ float g_lsum[(size_t)NNODE * HEADS];
__device__ float g_gsum[(size_t)NNODE * HEADS];

// ---------------- zero accumulators ----------------------------------------
__global__ void zero_kernel() {
    int i = blockIdx.x * blockDim.x + threadIdx.x;
    if (i < NNODE * 256) { g_lacc[i] = 0.f; g_gacc[i] = 0.f; }
    if (i < NNODE * HEADS) { g_lsum[i] = 0.f; g_gsum[i] = 0.f; }
}

// ---------------- helpers ----------------------------------------------------
__device__ __forceinline__ unsigned pack_bf16x2(float a, float b) {
    __nv_bfloat162 t = __float22bfloat162_rn(make_float2(a, b));
    return *reinterpret_cast<unsigned*>(&t);
}
__device__ __forceinline__ float bf16_hi(float x) {
    return __bfloat162float(__float2bfloat16_rn(x));
}
__device__ __forceinline__ void mma16(float* c, const unsigned* a, const unsigned* b) {
    asm volatile(
        "mma.sync.aligned.m16n8k16.row.col.f32.bf16.bf16.f32 "
        "{%0,%1,%2,%3},{%4,%5,%6,%7},{%8,%9},{%0,%1,%2,%3};\n"
        : "+f"(c[0]), "+f"(c[1]), "+f"(c[2]), "+f"(c[3])
        : "r"(a[0]), "r"(a[1]), "r"(a[2]), "r"(a[3]), "r"(b[0]), "r"(b[1]));
}

// ---------------- hand-mma split-bf16 GEMM -----------------------------------
// Block tile 128x64x32, 256 threads = 8 warps (4m x 2n), warp tile 32x32
// = 2mf x 4nf of m16n8k16. 3-term split: Ahi*Bhi + Alo*Bhi + Ahi*Blo.
// Smem (k-packed uint32 = {bf16 k even lo, k odd hi}):
//   A[h/l]: [m 0..127][kp 0..15] stride 20  (fragment LDS conflict-free)
//   B[h/l]: [kp 0..15][n 0..63]  stride 72  (fragment LDS conflict-free,
//            transpose-store via per-thread k-pair, STS.128, 2-phase)
// Epilogue: registers -> gmem direct (C frag layout: c0,c1=row tr cols 2tc,
// 2tc+1; c2,c3=row tr+8), no staging smem.
//
// MODE 0: C -> g_q   MODE 1: C -> g_k (+deg_emb on cols>=256)   MODE 5: C -> g_v
// MODE 2: split store -> g_ab / g_vb
// MODE 3: A = normalized [lacc|gacc] (K=512), C = param
// MODE 4: A = [f_bond | extra[idx[row]]] (K=512), C = param
#define BMT 128
#define BNT 64
#define BKT 32
#define ALD 20    // A stride in words
#define BLD 72    // B stride in words

template<int MODE>
__device__ __forceinline__ float4 loadA4(int gm, int gk, int M, int K,
                                         const float* __restrict__ A,
                                         const int* __restrict__ idx,
                                         const float* __restrict__ extra)
{
    if (gm >= M) return make_float4(0.f, 0.f, 0.f, 0.f);
    if (MODE == 3) {
        float4 v; float su;
        if (gk < 256) {
            su = g_lsum[gm * HEADS + (gk >> 5)];
            v = *reinterpret_cast<const float4*>(&g_lacc[(size_t)gm * 256 + gk]);
        } else {
            int jj = gk - 256;
            su = g_gsum[gm * HEADS + (jj >> 5)];
            v = *reinterpret_cast<const float4*>(&g_gacc[(size_t)gm * 256 + jj]);
        }
        float inv = (su > 0.f) ? 1.f / su : 0.f;
        v.x *= inv; v.y *= inv; v.z *= inv; v.w *= inv;
        return v;
    } else if (MODE == 4) {
        if (gk < 256) return *reinterpret_cast<const float4*>(&A[(size_t)gm * 256 + gk]);
        return *reinterpret_cast<const float4*>(&extra[(size_t)idx[gm] * 256 + (gk - 256)]);
    } else {
        return *reinterpret_cast<const float4*>(&A[(size_t)gm * K + gk]);
    }
}

template<int MODE>
__global__ void __launch_bounds__(256, 2) tgemm(
    int M, int K, int NN,
    const float* __restrict__ A, const float* __restrict__ B,
    const float* __restrict__ bias, float* __restrict__ Cparam,
    const int* __restrict__ idx, const float* __restrict__ extra,
    const int* __restrict__ deg, const float* __restrict__ deg_emb)
{
    float* C;
    if      (MODE == 0) C = g_q;
    else if (MODE == 1) C = g_k;
    else if (MODE == 5) C = g_v;
    else                C = Cparam;

    __shared__ unsigned Ahs[BMT * ALD], Als[BMT * ALD];
    __shared__ unsigned Bhs[16 * BLD],  Bls[16 * BLD];

    const int tid = threadIdx.x;
    const int m0 = blockIdx.y * BMT, n0 = blockIdx.x * BNT;
    const int warp = tid >> 5, lane = tid & 31;
    const int wm = (warp & 3) * 32, wn = (warp >> 2) * 32;
    const int tr = lane >> 2, tc = lane & 3;

    // A fill: thread -> row am, k-halves [ak0, ak0+16)
    const int am = tid >> 1, ak0 = (tid & 1) * 16, akp0 = (tid & 1) * 8;
    // B fill: thread -> k-pair kpb (rows 2kpb, 2kpb+1), n-chunk 4*ngb
    const int kpb = tid >> 4, ngb = tid & 15;

    float acc[2][4][4] = {};

    float4 pa[4], pb0, pb1;
#pragma unroll
    for (int i = 0; i < 4; i++)
        pa[i] = loadA4<MODE>(m0 + am, ak0 + 4 * i, M, K, A, idx, extra);
    pb0 = *reinterpret_cast<const float4*>(&B[(size_t)(2 * kpb)     * NN + n0 + 4 * ngb]);
    pb1 = *reinterpret_cast<const float4*>(&B[(size_t)(2 * kpb + 1) * NN + n0 + 4 * ngb]);

    for (int k0 = 0; k0 < K; k0 += BKT) {
        // ---- convert + store A (2 x STS.128 per array) ----
        {
            unsigned wh[8], wl[8];
#pragma unroll
            for (int i = 0; i < 4; i++) {
                float x0 = pa[i].x, x1 = pa[i].y, x2 = pa[i].z, x3 = pa[i].w;
                float h0 = bf16_hi(x0), h1 = bf16_hi(x1), h2 = bf16_hi(x2), h3 = bf16_hi(x3);
                wh[2*i]   = pack_bf16x2(x0, x1);       wh[2*i+1] = pack_bf16x2(x2, x3);
                wl[2*i]   = pack_bf16x2(x0-h0, x1-h1); wl[2*i+1] = pack_bf16x2(x2-h2, x3-h3);
            }
            uint4* dh = reinterpret_cast<uint4*>(&Ahs[am * ALD + akp0]);
            uint4* dl = reinterpret_cast<uint4*>(&Als[am * ALD + akp0]);
            dh[0] = make_uint4(wh[0], wh[1], wh[2], wh[3]);
            dh[1] = make_uint4(wh[4], wh[5], wh[6], wh[7]);
            dl[0] = make_uint4(wl[0], wl[1], wl[2], wl[3]);
            dl[1] = make_uint4(wl[4], wl[5], wl[6], wl[7]);
        }
        // ---- convert + transpose-store B (1 x STS.128 per array) ----
        {
            float bx[4] = {pb0.x, pb0.y, pb0.z, pb0.w};
            float by[4] = {pb1.x, pb1.y, pb1.z, pb1.w};
            unsigned wh[4], wl[4];
#pragma unroll
            for (int j = 0; j < 4; j++) {
                float h0 = bf16_hi(bx[j]), h1 = bf16_hi(by[j]);
                wh[j] = pack_bf16x2(bx[j], by[j]);
                wl[j] = pack_bf16x2(bx[j] - h0, by[j] - h1);
            }
            *reinterpret_cast<uint4*>(&Bhs[kpb * BLD + 4 * ngb]) =
                make_uint4(wh[0], wh[1], wh[2], wh[3]);
            *reinterpret_cast<uint4*>(&Bls[kpb * BLD + 4 * ngb]) =
                make_uint4(wl[0], wl[1], wl[2], wl[3]);
        }
        __syncthreads();

        // ---- prefetch next tile (overlaps MMA phase) ----
        if (k0 + BKT < K) {
#pragma unroll
            for (int i = 0; i < 4; i++)
                pa[i] = loadA4<MODE>(m0 + am, k0 + BKT + ak0 + 4 * i, M, K, A, idx, extra);
            pb0 = *reinterpret_cast<const float4*>(
                      &B[(size_t)(k0 + BKT + 2 * kpb)     * NN + n0 + 4 * ngb]);
            pb1 = *reinterpret_cast<const float4*>(
                      &B[(size_t)(k0 + BKT + 2 * kpb + 1) * NN + n0 + 4 * ngb]);
        }

        // ---- MMA phase: 2 k16 steps ----
#pragma unroll
        for (int ks = 0; ks < 2; ks++) {
            const int kp0 = ks * 8;
            unsigned ah[2][4], al[2][4];
#pragma unroll
            for (int mf = 0; mf < 2; mf++) {
                int mb = wm + mf * 16;
                ah[mf][0] = Ahs[(mb + tr)     * ALD + kp0 + tc];
                ah[mf][1] = Ahs[(mb + tr + 8) * ALD + kp0 + tc];
                ah[mf][2] = Ahs[(mb + tr)     * ALD + kp0 + tc + 4];
                ah[mf][3] = Ahs[(mb + tr + 8) * ALD + kp0 + tc + 4];
                al[mf][0] = Als[(mb + tr)     * ALD + kp0 + tc];
                al[mf][1] = Als[(mb + tr + 8) * ALD + kp0 + tc];
                al[mf][2] = Als[(mb + tr)     * ALD + kp0 + tc + 4];
                al[mf][3] = Als[(mb + tr + 8) * ALD + kp0 + tc + 4];
            }
#pragma unroll
            for (int nf = 0; nf < 4; nf++) {
                int nb = wn + nf * 8 + tr;
                unsigned bh[2], bl[2];
                bh[0] = Bhs[(kp0 + tc)     * BLD + nb];
                bh[1] = Bhs[(kp0 + tc + 4) * BLD + nb];
                bl[0] = Bls[(kp0 + tc)     * BLD + nb];
                bl[1] = Bls[(kp0 + tc + 4) * BLD + nb];
#pragma unroll
                for (int mf = 0; mf < 2; mf++) {
                    mma16(acc[mf][nf], ah[mf], bh);
                    mma16(acc[mf][nf], al[mf], bh);
                    mma16(acc[mf][nf], ah[mf], bl);
                }
            }
        }
        __syncthreads();
    }

    // ---- epilogue: direct register -> gmem ----
#pragma unroll
    for (int mf = 0; mf < 2; mf++) {
#pragma unroll
        for (int half = 0; half < 2; half++) {
            int gm = m0 + wm + mf * 16 + tr + half * 8;
            if (gm >= M) continue;
            int dg = (MODE == 1) ? deg[gm] : 0;
#pragma unroll
            for (int nf = 0; nf < 4; nf++) {
#pragma unroll
                for (int jj = 0; jj < 2; jj++) {
                    int gn = n0 + wn + nf * 8 + tc * 2 + jj;
                    float val = acc[mf][nf][half * 2 + jj] + bias[gn];
                    if (MODE == 1) {
                        if (gn >= 256) val += deg_emb[(size_t)dg * 256 + (gn - 256)];
                        C[(size_t)gm * NN + gn] = val;
                    } else if (MODE == 2) {
                        if (gn < 256) g_ab[(size_t)gm * 256 + gn] = val;
                        else          g_vb[(size_t)gm * 256 + (gn - 256)] = val;
                    } else {
                        C[(size_t)gm * NN + gn] = val;
                    }
                }
            }
        }
    }
}

// ---------------- local attention (grid-stride, 256 thr = 1 edge) ------------
__global__ void local_att(const int* __restrict__ bond_idx)
{
    int t = threadIdx.x;  // head = t>>5, dim = t&31
    for (int e = blockIdx.x; e < ELOCAL; e += gridDim.x) {
        int src = __ldg(&bond_idx[e]);
        int dst = __ldg(&bond_idx[ELOCAL + e]);
        float qv = g_q[(size_t)dst * 512 + t];
        float kv = g_k[(size_t)src * 512 + t];
        float vv = g_v[(size_t)src * 512 + t];
        float prod = qv * kv;
        if (e < EBOND) {
            prod += g_ab[(size_t)e * 256 + t];
            vv   += g_vb[(size_t)e * 256 + t];
        }
        float s = prod;
#pragma unroll
        for (int o = 16; o; o >>= 1) s += __shfl_xor_sync(0xffffffffu, s, o);
        float es = __expf(s * SCALE);
        atomicAdd(&g_lacc[(size_t)dst * 256 + t], es * vv);
        if ((t & 31) == 0) atomicAdd(&g_lsum[dst * HEADS + (t >> 5)], es);
    }
}

// ---------------- global attention (grid-stride, 256 thr = 1 edge) -----------
__global__ void global_att(const int* __restrict__ qi, const int* __restrict__ ki,
                           const int* __restrict__ dist, const float* __restrict__ dist_emb)
{
    int t = threadIdx.x;
    for (int e = blockIdx.x; e < EGLOBAL; e += gridDim.x) {
        int q = __ldg(&qi[e]);
        int k = __ldg(&ki[e]);
        int dd = __ldg(&dist[e]);
        float prod = g_q[(size_t)q * 512 + 256 + t] * g_k[(size_t)k * 512 + 256 + t]
                   + __ldg(&dist_emb[(size_t)dd * 256 + t]);
        if (e < EBOND) prod += g_ab[(size_t)e * 256 + t];
        float s = prod;
#pragma unroll
        for (int o = 16; o; o >>= 1) s += __shfl_xor_sync(0xffffffffu, s, o);
        float es = __expf(s * SCALE);
        float vv = g_v[(size_t)k * 512 + 256 + t];
        atomicAdd(&g_gacc[(size_t)q * 256 + t], es * vv);
        if ((t & 31) == 0) atomicAdd(&g_gsum[q * HEADS + (t >> 5)], es);
    }
}

// ---------------- launch -----------------------------------------------------
extern "C" void kernel_launch(void* const* d_in, const int* in_sizes, int n_in,
                              void* d_out, int out_size)
{
    const float* f_node   = (const float*)d_in[0];
    const float* f_bond   = (const float*)d_in[1];
    const int*   deg      = (const int*)d_in[2];
    const int*   dist     = (const int*)d_in[3];
    const int*   bond_idx = (const int*)d_in[4];
    const int*   query_ix = (const int*)d_in[5];
    const int*   key_ix   = (const int*)d_in[6];
    // d_in[7] attention_bond_idx == arange(E_BOND) (positional identity)
    const float* deg_emb  = (const float*)d_in[8];
    const float* dist_emb = (const float*)d_in[9];
    const float* Wq_w = (const float*)d_in[10]; const float* Wq_b = (const float*)d_in[11];
    const float* Wk_w = (const float*)d_in[12]; const float* Wk_b = (const float*)d_in[13];
    const float* Wv_w = (const float*)d_in[14]; const float* Wv_b = (const float*)d_in[15];
    const float* out_w = (const float*)d_in[16]; const float* out_b = (const float*)d_in[17];
    const float* be_w = (const float*)d_in[18]; const float* be_b = (const float*)d_in[19];
    const float* bu_w = (const float*)d_in[20]; const float* bu_b = (const float*)d_in[21];

    float* out      = (float*)d_out;                      // (NNODE, 256)
    float* bond_out = out + (size_t)NNODE * 256;          // (EBOND, 256)

    zero_kernel<<<(NNODE * 256 + 255) / 256, 256>>>();

    dim3 gN512(512 / BNT, (NNODE + BMT - 1) / BMT);
    dim3 gE512(512 / BNT, (EBOND + BMT - 1) / BMT);
    dim3 gN256(256 / BNT, (NNODE + BMT - 1) / BMT);
    dim3 gE256(256 / BNT, (EBOND + BMT - 1) / BMT);

    // q/k/v: M=NNODE, K=256, NN=512 (destinations resolved device-side by MODE)
    tgemm<0><<<gN512, 256>>>(NNODE, 256, 512, f_node, Wq_w, Wq_b, nullptr,
                             nullptr, nullptr, nullptr, nullptr);
    tgemm<1><<<gN512, 256>>>(NNODE, 256, 512, f_node, Wk_w, Wk_b, nullptr,
                             nullptr, nullptr, deg, deg_emb);
    tgemm<5><<<gN512, 256>>>(NNODE, 256, 512, f_node, Wv_w, Wv_b, nullptr,
                             nullptr, nullptr, nullptr, nullptr);

    // bond embedding: M=EBOND, K=256, NN=512 -> g_ab / g_vb (device-internal)
    tgemm<2><<<gE512, 256>>>(EBOND, 256, 512, f_bond, be_w, be_b, nullptr,
                             nullptr, nullptr, nullptr, nullptr);

    local_att<<<4096, 256>>>(bond_idx);
    global_att<<<8192, 256>>>(query_ix, key_ix, dist, dist_emb);

    // out = [lacc/lsum | gacc/gsum] @ out_w + out_b : M=NNODE, K=512, NN=256
    tgemm<3><<<gN256, 256>>>(NNODE, 512, 256, nullptr, out_w, out_b, out,
                             nullptr, nullptr, nullptr, nullptr);

    // bond_out = [f_bond | out[src]] @ bu_w + bu_b : M=EBOND, K=512, NN=256
    tgemm<4><<<gE256, 256>>>(EBOND, 512, 256, f_bond, bu_w, bu_b, bond_out,
                             bond_idx, out, nullptr, nullptr);
}

// round 14
// speedup vs baseline: 2.1113x; 1.0232x over previous
#include <cuda_runtime.h>
#include <cuda_bf16.h>
#include <math.h>

#define HEADS 8
#define DHEAD 32
#define DMODEL 256
#define NNODE 20000
#define ELOCAL 80000
#define EBOND 60000
#define EGLOBAL 400000
#define SCALE 0.17677669529663687f  // 1/sqrt(32)

// ---------------- scratch (device globals; no allocation allowed) ----------
// NOTE: never pass these as kernel arguments from HOST code — the host sees
// the shadow-object address and GB300 ATS dereferences it silently (R4-R6 bug).
__device__ float g_q[(size_t)NNODE * 512];
__device__ float g_k[(size_t)NNODE * 512];   // global half already includes deg_emb
__device__ float g_v[(size_t)NNODE * 512];
__device__ float g_ab[(size_t)EBOND * 256];  // attention_bond
__device__ float g_vb[(size_t)EBOND * 256];  // value_bond
__device__ float g_lacc[(size_t)NNODE * 256];
__device__ float g_gacc[(size_t)NNODE * 256];
__device__ float g_lsum[(size_t)NNODE * HEADS];
__device__ float g_gsum[(size_t)NNODE * HEADS];

// ---------------- zero accumulators ----------------------------------------
__global__ void zero_kernel() {
    int i = blockIdx.x * blockDim.x + threadIdx.x;
    if (i < NNODE * 256) { g_lacc[i] = 0.f; g_gacc[i] = 0.f; }
    if (i < NNODE * HEADS) { g_lsum[i] = 0.f; g_gsum[i] = 0.f; }
}

// ---------------- helpers ----------------------------------------------------
__device__ __forceinline__ unsigned pack_bf16x2(float a, float b) {
    __nv_bfloat162 t = __float22bfloat162_rn(make_float2(a, b));
    return *reinterpret_cast<unsigned*>(&t);
}
__device__ __forceinline__ float bf16_hi(float x) {
    return __bfloat162float(__float2bfloat16_rn(x));
}
__device__ __forceinline__ void mma16(float* c, const unsigned* a, const unsigned* b) {
    asm volatile(
        "mma.sync.aligned.m16n8k16.row.col.f32.bf16.bf16.f32 "
        "{%0,%1,%2,%3},{%4,%5,%6,%7},{%8,%9},{%0,%1,%2,%3};\n"
        : "+f"(c[0]), "+f"(c[1]), "+f"(c[2]), "+f"(c[3])
        : "r"(a[0]), "r"(a[1]), "r"(a[2]), "r"(a[3]), "r"(b[0]), "r"(b[1]));
}
__device__ __forceinline__ void ldsm4(unsigned &r0, unsigned &r1, unsigned &r2,
                                      unsigned &r3, unsigned saddr) {
    asm volatile("ldmatrix.sync.aligned.m8n8.x4.shared.b16 {%0,%1,%2,%3}, [%4];"
        : "=r"(r0), "=r"(r1), "=r"(r2), "=r"(r3) : "r"(saddr));
}

// ---------------- hand-mma split-bf16 GEMM (ldmatrix loaders) ----------------
// Block tile 128x64x32, 256 threads = 8 warps (4m x 2n), warp tile 32x32
// = 2mf x 4nf of m16n8k16. 3-term split: Ahi*Bhi + Alo*Bhi + Ahi*Blo.
// Smem (k-packed uint32 = {bf16 k even lo, k odd hi}), both stride 20 words:
//   A[h/l]: [m 0..127][kp 0..15]  B[h/l]: [n 0..63][kp 0..15]
// Stride 20 -> LDSM row chunks hit distinct bank quartets (conflict-free).
// Fragment loads: ldmatrix.x4 (same word content as the R13-validated map).
//
// MODE 0: C -> g_q   MODE 1: C -> g_k (+deg_emb on cols>=256)   MODE 5: C -> g_v
// MODE 2: split store -> g_ab / g_vb
// MODE 3: A = normalized [lacc|gacc] (K=512), C = param
// MODE 4: A = [f_bond | extra[idx[row]]] (K=512), C = param
#define BMT 128
#define BNT 64
#define BKT 32
#define ALD 20
#define BLD2 20

template<int MODE>
__device__ __forceinline__ float4 loadA4(int gm, int gk, int M, int K,
                                         const float* __restrict__ A,
                                         const int* __restrict__ idx,
                                         const float* __restrict__ extra)
{
    if (gm >= M) return make_float4(0.f, 0.f, 0.f, 0.f);
    if (MODE == 3) {
        float4 v; float su;
        if (gk < 256) {
            su = g_lsum[gm * HEADS + (gk >> 5)];
            v = *reinterpret_cast<const float4*>(&g_lacc[(size_t)gm * 256 + gk]);
        } else {
            int jj = gk - 256;
            su = g_gsum[gm * HEADS + (jj >> 5)];
            v = *reinterpret_cast<const float4*>(&g_gacc[(size_t)gm * 256 + jj]);
        }
        float inv = (su > 0.f) ? 1.f / su : 0.f;
        v.x *= inv; v.y *= inv; v.z *= inv; v.w *= inv;
        return v;
    } else if (MODE == 4) {
        if (gk < 256) return *reinterpret_cast<const float4*>(&A[(size_t)gm * 256 + gk]);
        return *reinterpret_cast<const float4*>(&extra[(size_t)idx[gm] * 256 + (gk - 256)]);
    } else {
        return *reinterpret_cast<const float4*>(&A[(size_t)gm * K + gk]);
    }
}

template<int MODE>
__global__ void __launch_bounds__(256, 2) tgemm(
    int M, int K, int NN,
    const float* __restrict__ A, const float* __restrict__ B,
    const float* __restrict__ bias, float* __restrict__ Cparam,
    const int* __restrict__ idx, const float* __restrict__ extra,
    const int* __restrict__ deg, const float* __restrict__ deg_emb)
{
    float* C;
    if      (MODE == 0) C = g_q;
    else if (MODE == 1) C = g_k;
    else if (MODE == 5) C = g_v;
    else                C = Cparam;

    __shared__ unsigned Ahs[BMT * ALD], Als[BMT * ALD];
    __shared__ unsigned Bhs[BNT * BLD2], Bls[BNT * BLD2];

    const int tid = threadIdx.x;
    const int m0 = blockIdx.y * BMT, n0 = blockIdx.x * BNT;
    const int warp = tid >> 5, lane = tid & 31;
    const int wm = (warp & 3) * 32, wn = (warp >> 2) * 32;
    const int tr = lane >> 2, tc = lane & 3;

    // A fill: thread -> row am, k-halves [ak0, ak0+16)
    const int am = tid >> 1, ak0 = (tid & 1) * 16, akp0 = (tid & 1) * 8;
    // B fill: thread -> k-pair kpb (rows 2kpb, 2kpb+1), n strided: ngb + 16j
    const int kpb = tid >> 4, ngb = tid & 15;

    // LDSM lane addressing (precomputed row/word offsets within a tile)
    const int rowA = (lane & 7) + 8 * ((lane >> 3) & 1);
    const int kA   = 4 * (lane >> 4);
    const int rowB = (lane & 7) + 8 * (lane >> 4);
    const int kB   = 4 * ((lane >> 3) & 1);

    const unsigned sAh = (unsigned)__cvta_generic_to_shared(Ahs);
    const unsigned sAl = (unsigned)__cvta_generic_to_shared(Als);
    const unsigned sBh = (unsigned)__cvta_generic_to_shared(Bhs);
    const unsigned sBl = (unsigned)__cvta_generic_to_shared(Bls);

    float acc[2][4][4] = {};

    float4 pa[4];
    float pbx[4], pby[4];
#pragma unroll
    for (int i = 0; i < 4; i++)
        pa[i] = loadA4<MODE>(m0 + am, ak0 + 4 * i, M, K, A, idx, extra);
#pragma unroll
    for (int j = 0; j < 4; j++) {
        pbx[j] = B[(size_t)(2 * kpb)     * NN + n0 + ngb + 16 * j];
        pby[j] = B[(size_t)(2 * kpb + 1) * NN + n0 + ngb + 16 * j];
    }

    for (int k0 = 0; k0 < K; k0 += BKT) {
        // ---- convert + store A (2 x STS.128 per array) ----
        {
            unsigned wh[8], wl[8];
#pragma unroll
            for (int i = 0; i < 4; i++) {
                float x0 = pa[i].x, x1 = pa[i].y, x2 = pa[i].z, x3 = pa[i].w;
                float h0 = bf16_hi(x0), h1 = bf16_hi(x1), h2 = bf16_hi(x2), h3 = bf16_hi(x3);
                wh[2*i]   = pack_bf16x2(x0, x1);       wh[2*i+1] = pack_bf16x2(x2, x3);
                wl[2*i]   = pack_bf16x2(x0-h0, x1-h1); wl[2*i+1] = pack_bf16x2(x2-h2, x3-h3);
            }
            uint4* dh = reinterpret_cast<uint4*>(&Ahs[am * ALD + akp0]);
            uint4* dl = reinterpret_cast<uint4*>(&Als[am * ALD + akp0]);
            dh[0] = make_uint4(wh[0], wh[1], wh[2], wh[3]);
            dh[1] = make_uint4(wh[4], wh[5], wh[6], wh[7]);
            dl[0] = make_uint4(wl[0], wl[1], wl[2], wl[3]);
            dl[1] = make_uint4(wl[4], wl[5], wl[6], wl[7]);
        }
        // ---- convert + transpose-store B -> [n][kp] ----
#pragma unroll
        for (int j = 0; j < 4; j++) {
            float h0 = bf16_hi(pbx[j]), h1 = bf16_hi(pby[j]);
            int nrow = ngb + 16 * j;
            Bhs[nrow * BLD2 + kpb] = pack_bf16x2(pbx[j], pby[j]);
            Bls[nrow * BLD2 + kpb] = pack_bf16x2(pbx[j] - h0, pby[j] - h1);
        }
        __syncthreads();

        // ---- prefetch next tile (overlaps MMA phase) ----
        if (k0 + BKT < K) {
#pragma unroll
            for (int i = 0; i < 4; i++)
                pa[i] = loadA4<MODE>(m0 + am, k0 + BKT + ak0 + 4 * i, M, K, A, idx, extra);
#pragma unroll
            for (int j = 0; j < 4; j++) {
                pbx[j] = B[(size_t)(k0 + BKT + 2 * kpb)     * NN + n0 + ngb + 16 * j];
                pby[j] = B[(size_t)(k0 + BKT + 2 * kpb + 1) * NN + n0 + ngb + 16 * j];
            }
        }

        // ---- MMA phase: 2 k16 steps, fragments via ldmatrix.x4 ----
#pragma unroll
        for (int ks = 0; ks < 2; ks++) {
            const int kp0 = ks * 8;
            unsigned ah[2][4], al[2][4];
#pragma unroll
            for (int mf = 0; mf < 2; mf++) {
                unsigned offA = ((wm + mf * 16 + rowA) * ALD + kp0 + kA) * 4u;
                ldsm4(ah[mf][0], ah[mf][1], ah[mf][2], ah[mf][3], sAh + offA);
                ldsm4(al[mf][0], al[mf][1], al[mf][2], al[mf][3], sAl + offA);
            }
            unsigned bh[4][2], bl[4][2];
#pragma unroll
            for (int nfp = 0; nfp < 2; nfp++) {
                unsigned offB = ((wn + nfp * 16 + rowB) * BLD2 + kp0 + kB) * 4u;
                ldsm4(bh[2*nfp][0], bh[2*nfp][1], bh[2*nfp+1][0], bh[2*nfp+1][1], sBh + offB);
                ldsm4(bl[2*nfp][0], bl[2*nfp][1], bl[2*nfp+1][0], bl[2*nfp+1][1], sBl + offB);
            }
#pragma unroll
            for (int nf = 0; nf < 4; nf++)
#pragma unroll
                for (int mf = 0; mf < 2; mf++) {
                    mma16(acc[mf][nf], ah[mf], bh[nf]);
                    mma16(acc[mf][nf], al[mf], bh[nf]);
                    mma16(acc[mf][nf], ah[mf], bl[nf]);
                }
        }
        __syncthreads();
    }

    // ---- epilogue: direct register -> gmem ----
#pragma unroll
    for (int mf = 0; mf < 2; mf++) {
#pragma unroll
        for (int half = 0; half < 2; half++) {
            int gm = m0 + wm + mf * 16 + tr + half * 8;
            if (gm >= M) continue;
            int dg = (MODE == 1) ? deg[gm] : 0;
#pragma unroll
            for (int nf = 0; nf < 4; nf++) {
#pragma unroll
                for (int jj = 0; jj < 2; jj++) {
                    int gn = n0 + wn + nf * 8 + tc * 2 + jj;
                    float val = acc[mf][nf][half * 2 + jj] + bias[gn];
                    if (MODE == 1) {
                        if (gn >= 256) val += deg_emb[(size_t)dg * 256 + (gn - 256)];
                        C[(size_t)gm * NN + gn] = val;
                    } else if (MODE == 2) {
                        if (gn < 256) g_ab[(size_t)gm * 256 + gn] = val;
                        else          g_vb[(size_t)gm * 256 + (gn - 256)] = val;
                    } else {
                        C[(size_t)gm * NN + gn] = val;
                    }
                }
            }
        }
    }
}

// ---------------- local attention (grid-stride, 256 thr = 1 edge) ------------
__global__ void local_att(const int* __restrict__ bond_idx)
{
    int t = threadIdx.x;  // head = t>>5, dim = t&31
    for (int e = blockIdx.x; e < ELOCAL; e += gridDim.x) {
        int src = __ldg(&bond_idx[e]);
        int dst = __ldg(&bond_idx[ELOCAL + e]);
        float qv = g_q[(size_t)dst * 512 + t];
        float kv = g_k[(size_t)src * 512 + t];
        float vv = g_v[(size_t)src * 512 + t];
        float prod = qv * kv;
        if (e < EBOND) {
            prod += g_ab[(size_t)e * 256 + t];
            vv   += g_vb[(size_t)e * 256 + t];
        }
        float s = prod;
#pragma unroll
        for (int o = 16; o; o >>= 1) s += __shfl_xor_sync(0xffffffffu, s, o);
        float es = __expf(s * SCALE);
        atomicAdd(&g_lacc[(size_t)dst * 256 + t], es * vv);
        if ((t & 31) == 0) atomicAdd(&g_lsum[dst * HEADS + (t >> 5)], es);
    }
}

// ---------------- global attention (grid-stride, 256 thr = 1 edge) -----------
__global__ void global_att(const int* __restrict__ qi, const int* __restrict__ ki,
                           const int* __restrict__ dist, const float* __restrict__ dist_emb)
{
    int t = threadIdx.x;
    for (int e = blockIdx.x; e < EGLOBAL; e += gridDim.x) {
        int q = __ldg(&qi[e]);
        int k = __ldg(&ki[e]);
        int dd = __ldg(&dist[e]);
        float prod = g_q[(size_t)q * 512 + 256 + t] * g_k[(size_t)k * 512 + 256 + t]
                   + __ldg(&dist_emb[(size_t)dd * 256 + t]);
        if (e < EBOND) prod += g_ab[(size_t)e * 256 + t];
        float s = prod;
#pragma unroll
        for (int o = 16; o; o >>= 1) s += __shfl_xor_sync(0xffffffffu, s, o);
        float es = __expf(s * SCALE);
        float vv = g_v[(size_t)k * 512 + 256 + t];
        atomicAdd(&g_gacc[(size_t)q * 256 + t], es * vv);
        if ((t & 31) == 0) atomicAdd(&g_gsum[q * HEADS + (t >> 5)], es);
    }
}

// ---------------- launch -----------------------------------------------------
extern "C" void kernel_launch(void* const* d_in, const int* in_sizes, int n_in,
                              void* d_out, int out_size)
{
    const float* f_node   = (const float*)d_in[0];
    const float* f_bond   = (const float*)d_in[1];
    const int*   deg      = (const int*)d_in[2];
    const int*   dist     = (const int*)d_in[3];
    const int*   bond_idx = (const int*)d_in[4];
    const int*   query_ix = (const int*)d_in[5];
    const int*   key_ix   = (const int*)d_in[6];
    // d_in[7] attention_bond_idx == arange(E_BOND) (positional identity)
    const float* deg_emb  = (const float*)d_in[8];
    const float* dist_emb = (const float*)d_in[9];
    const float* Wq_w = (const float*)d_in[10]; const float* Wq_b = (const float*)d_in[11];
    const float* Wk_w = (const float*)d_in[12]; const float* Wk_b = (const float*)d_in[13];
    const float* Wv_w = (const float*)d_in[14]; const float* Wv_b = (const float*)d_in[15];
    const float* out_w = (const float*)d_in[16]; const float* out_b = (const float*)d_in[17];
    const float* be_w = (const float*)d_in[18]; const float* be_b = (const float*)d_in[19];
    const float* bu_w = (const float*)d_in[20]; const float* bu_b = (const float*)d_in[21];

    float* out      = (float*)d_out;                      // (NNODE, 256)
    float* bond_out = out + (size_t)NNODE * 256;          // (EBOND, 256)

    zero_kernel<<<(NNODE * 256 + 255) / 256, 256>>>();

    dim3 gN512(512 / BNT, (NNODE + BMT - 1) / BMT);
    dim3 gE512(512 / BNT, (EBOND + BMT - 1) / BMT);
    dim3 gN256(256 / BNT, (NNODE + BMT - 1) / BMT);
    dim3 gE256(256 / BNT, (EBOND + BMT - 1) / BMT);

    // q/k/v: M=NNODE, K=256, NN=512 (destinations resolved device-side by MODE)
    tgemm<0><<<gN512, 256>>>(NNODE, 256, 512, f_node, Wq_w, Wq_b, nullptr,
                             nullptr, nullptr, nullptr, nullptr);
    tgemm<1><<<gN512, 256>>>(NNODE, 256, 512, f_node, Wk_w, Wk_b, nullptr,
                             nullptr, nullptr, deg, deg_emb);
    tgemm<5><<<gN512, 256>>>(NNODE, 256, 512, f_node, Wv_w, Wv_b, nullptr,
                             nullptr, nullptr, nullptr, nullptr);

    // bond embedding: M=EBOND, K=256, NN=512 -> g_ab / g_vb (device-internal)
    tgemm<2><<<gE512, 256>>>(EBOND, 256, 512, f_bond, be_w, be_b, nullptr,
                             nullptr, nullptr, nullptr, nullptr);

    local_att<<<4096, 256>>>(bond_idx);
    global_att<<<8192, 256>>>(query_ix, key_ix, dist, dist_emb);

    // out = [lacc/lsum | gacc/gsum] @ out_w + out_b : M=NNODE, K=512, NN=256
    tgemm<3><<<gN256, 256>>>(NNODE, 512, 256, nullptr, out_w, out_b, out,
                             nullptr, nullptr, nullptr, nullptr);

    // bond_out = [f_bond | out[src]] @ bu_w + bu_b : M=EBOND, K=512, NN=256
    tgemm<4><<<gE256, 256>>>(EBOND, 512, 256, f_bond, bu_w, bu_b, bond_out,
                             bond_idx, out, nullptr, nullptr);
}

// round 17
// speedup vs baseline: 2.3669x; 1.1210x over previous
#include <cuda_runtime.h>
#include <cuda_bf16.h>
#include <math.h>

#define HEADS 8
#define NNODE 20000
#define ELOCAL 80000
#define EBOND 60000
#define EGLOBAL 400000
#define SCALE 0.17677669529663687f  // 1/sqrt(32)

// ---------------- scratch (device globals; no allocation allowed) ----------
// NOTE: never pass these as kernel arguments from HOST code — the host sees
// the shadow-object address and GB300 ATS dereferences it silently (R4-R6 bug).
__device__ float g_q[(size_t)NNODE * 512];
__device__ float g_k[(size_t)NNODE * 512];   // global half already includes deg_emb
__device__ float g_v[(size_t)NNODE * 512];
__device__ float g_ab[(size_t)EBOND * 256];  // attention_bond
__device__ float g_vb[(size_t)EBOND * 256];  // value_bond
__device__ float g_lacc[(size_t)NNODE * 256];
__device__ float g_gacc[(size_t)NNODE * 256];
__device__ float g_lsum[NNODE * HEADS];
__device__ float g_gsum[NNODE * HEADS];
// ---- edge sort scratch ----
__device__ int  g_cnt_g[NNODE], g_cnt_l[NNODE];
__device__ int  g_off_g[NNODE + 1], g_off_l[NNODE + 1];
__device__ int  g_cur_g[NNODE], g_cur_l[NNODE];
__device__ int4 g_ep_g[EGLOBAL];   // {key, dist, e, -}
__device__ int2 g_ep_l[ELOCAL];    // {src, e}

// ---------------- helpers ----------------------------------------------------
__device__ __forceinline__ unsigned pack_bf16x2(float a, float b) {
    __nv_bfloat162 t = __float22bfloat162_rn(make_float2(a, b));
    return *reinterpret_cast<unsigned*>(&t);
}
__device__ __forceinline__ float bf16_hi(float x) {
    return __bfloat162float(__float2bfloat16_rn(x));
}
__device__ __forceinline__ void mma16(float* c, const unsigned* a, const unsigned* b) {
    asm volatile(
        "mma.sync.aligned.m16n8k16.row.col.f32.bf16.bf16.f32 "
        "{%0,%1,%2,%3},{%4,%5,%6,%7},{%8,%9},{%0,%1,%2,%3};\n"
        : "+f"(c[0]), "+f"(c[1]), "+f"(c[2]), "+f"(c[3])
        : "r"(a[0]), "r"(a[1]), "r"(a[2]), "r"(a[3]), "r"(b[0]), "r"(b[1]));
}
__device__ __forceinline__ void ldsm4(unsigned &r0, unsigned &r1, unsigned &r2,
                                      unsigned &r3, unsigned saddr) {
    asm volatile("ldmatrix.sync.aligned.m8n8.x4.shared.b16 {%0,%1,%2,%3}, [%4];"
        : "=r"(r0), "=r"(r1), "=r"(r2), "=r"(r3) : "r"(saddr));
}

// ---------------- hand-mma split-bf16 GEMM (R14, unchanged) ------------------
#define BMT 128
#define BNT 64
#define BKT 32
#define ALD 20
#define BLD2 20

template<int MODE>
__device__ __forceinline__ float4 loadA4(int gm, int gk, int M, int K,
                                         const float* __restrict__ A,
                                         const int* __restrict__ idx,
                                         const float* __restrict__ extra)
{
    if (gm >= M) return make_float4(0.f, 0.f, 0.f, 0.f);
    if (MODE == 3) {
        float4 v; float su;
        if (gk < 256) {
            su = g_lsum[gm * HEADS + (gk >> 5)];
            v = *reinterpret_cast<const float4*>(&g_lacc[(size_t)gm * 256 + gk]);
        } else {
            int jj = gk - 256;
            su = g_gsum[gm * HEADS + (jj >> 5)];
            v = *reinterpret_cast<const float4*>(&g_gacc[(size_t)gm * 256 + jj]);
        }
        float inv = (su > 0.f) ? 1.f / su : 0.f;
        v.x *= inv; v.y *= inv; v.z *= inv; v.w *= inv;
        return v;
    } else if (MODE == 4) {
        if (gk < 256) return *reinterpret_cast<const float4*>(&A[(size_t)gm * 256 + gk]);
        return *reinterpret_cast<const float4*>(&extra[(size_t)idx[gm] * 256 + (gk - 256)]);
    } else {
        return *reinterpret_cast<const float4*>(&A[(size_t)gm * K + gk]);
    }
}

template<int MODE>
__global__ void __launch_bounds__(256, 2) tgemm(
    int M, int K, int NN,
    const float* __restrict__ A, const float* __restrict__ B,
    const float* __restrict__ bias, float* __restrict__ Cparam,
    const int* __restrict__ idx, const float* __restrict__ extra,
    const int* __restrict__ deg, const float* __restrict__ deg_emb)
{
    float* C;
    if      (MODE == 0) C = g_q;
    else if (MODE == 1) C = g_k;
    else if (MODE == 5) C = g_v;
    else                C = Cparam;

    __shared__ unsigned Ahs[BMT * ALD], Als[BMT * ALD];
    __shared__ unsigned Bhs[BNT * BLD2], Bls[BNT * BLD2];

    const int tid = threadIdx.x;
    const int m0 = blockIdx.y * BMT, n0 = blockIdx.x * BNT;
    const int warp = tid >> 5, lane = tid & 31;
    const int wm = (warp & 3) * 32, wn = (warp >> 2) * 32;
    const int tr = lane >> 2, tc = lane & 3;

    const int am = tid >> 1, ak0 = (tid & 1) * 16, akp0 = (tid & 1) * 8;
    const int kpb = tid >> 4, ngb = tid & 15;

    const int rowA = (lane & 7) + 8 * ((lane >> 3) & 1);
    const int kA   = 4 * (lane >> 4);
    const int rowB = (lane & 7) + 8 * (lane >> 4);
    const int kB   = 4 * ((lane >> 3) & 1);

    const unsigned sAh = (unsigned)__cvta_generic_to_shared(Ahs);
    const unsigned sAl = (unsigned)__cvta_generic_to_shared(Als);
    const unsigned sBh = (unsigned)__cvta_generic_to_shared(Bhs);
    const unsigned sBl = (unsigned)__cvta_generic_to_shared(Bls);

    float acc[2][4][4] = {};

    float4 pa[4];
    float pbx[4], pby[4];
#pragma unroll
    for (int i = 0; i < 4; i++)
        pa[i] = loadA4<MODE>(m0 + am, ak0 + 4 * i, M, K, A, idx, extra);
#pragma unroll
    for (int j = 0; j < 4; j++) {
        pbx[j] = B[(size_t)(2 * kpb)     * NN + n0 + ngb + 16 * j];
        pby[j] = B[(size_t)(2 * kpb + 1) * NN + n0 + ngb + 16 * j];
    }

    for (int k0 = 0; k0 < K; k0 += BKT) {
        {
            unsigned wh[8], wl[8];
#pragma unroll
            for (int i = 0; i < 4; i++) {
                float x0 = pa[i].x, x1 = pa[i].y, x2 = pa[i].z, x3 = pa[i].w;
                float h0 = bf16_hi(x0), h1 = bf16_hi(x1), h2 = bf16_hi(x2), h3 = bf16_hi(x3);
                wh[2*i]   = pack_bf16x2(x0, x1);       wh[2*i+1] = pack_bf16x2(x2, x3);
                wl[2*i]   = pack_bf16x2(x0-h0, x1-h1); wl[2*i+1] = pack_bf16x2(x2-h2, x3-h3);
            }
            uint4* dh = reinterpret_cast<uint4*>(&Ahs[am * ALD + akp0]);
            uint4* dl = reinterpret_cast<uint4*>(&Als[am * ALD + akp0]);
            dh[0] = make_uint4(wh[0], wh[1], wh[2], wh[3]);
            dh[1] = make_uint4(wh[4], wh[5], wh[6], wh[7]);
            dl[0] = make_uint4(wl[0], wl[1], wl[2], wl[3]);
            dl[1] = make_uint4(wl[4], wl[5], wl[6], wl[7]);
        }
#pragma unroll
        for (int j = 0; j < 4; j++) {
            float h0 = bf16_hi(pbx[j]), h1 = bf16_hi(pby[j]);
            int nrow = ngb + 16 * j;
            Bhs[nrow * BLD2 + kpb] = pack_bf16x2(pbx[j], pby[j]);
            Bls[nrow * BLD2 + kpb] = pack_bf16x2(pbx[j] - h0, pby[j] - h1);
        }
        __syncthreads();

        if (k0 + BKT < K) {
#pragma unroll
            for (int i = 0; i < 4; i++)
                pa[i] = loadA4<MODE>(m0 + am, k0 + BKT + ak0 + 4 * i, M, K, A, idx, extra);
#pragma unroll
            for (int j = 0; j < 4; j++) {
                pbx[j] = B[(size_t)(k0 + BKT + 2 * kpb)     * NN + n0 + ngb + 16 * j];
                pby[j] = B[(size_t)(k0 + BKT + 2 * kpb + 1) * NN + n0 + ngb + 16 * j];
            }
        }

#pragma unroll
        for (int ks = 0; ks < 2; ks++) {
            const int kp0 = ks * 8;
            unsigned ah[2][4], al[2][4];
#pragma unroll
            for (int mf = 0; mf < 2; mf++) {
                unsigned offA = ((wm + mf * 16 + rowA) * ALD + kp0 + kA) * 4u;
                ldsm4(ah[mf][0], ah[mf][1], ah[mf][2], ah[mf][3], sAh + offA);
                ldsm4(al[mf][0], al[mf][1], al[mf][2], al[mf][3], sAl + offA);
            }
            unsigned bh[4][2], bl[4][2];
#pragma unroll
            for (int nfp = 0; nfp < 2; nfp++) {
                unsigned offB = ((wn + nfp * 16 + rowB) * BLD2 + kp0 + kB) * 4u;
                ldsm4(bh[2*nfp][0], bh[2*nfp][1], bh[2*nfp+1][0], bh[2*nfp+1][1], sBh + offB);
                ldsm4(bl[2*nfp][0], bl[2*nfp][1], bl[2*nfp+1][0], bl[2*nfp+1][1], sBl + offB);
            }
#pragma unroll
            for (int nf = 0; nf < 4; nf++)
#pragma unroll
                for (int mf = 0; mf < 2; mf++) {
                    mma16(acc[mf][nf], ah[mf], bh[nf]);
                    mma16(acc[mf][nf], al[mf], bh[nf]);
                    mma16(acc[mf][nf], ah[mf], bl[nf]);
                }
        }
        __syncthreads();
    }

#pragma unroll
    for (int mf = 0; mf < 2; mf++) {
#pragma unroll
        for (int half = 0; half < 2; half++) {
            int gm = m0 + wm + mf * 16 + tr + half * 8;
            if (gm >= M) continue;
            int dg = (MODE == 1) ? deg[gm] : 0;
#pragma unroll
            for (int nf = 0; nf < 4; nf++) {
#pragma unroll
                for (int jj = 0; jj < 2; jj++) {
                    int gn = n0 + wn + nf * 8 + tc * 2 + jj;
                    float val = acc[mf][nf][half * 2 + jj] + bias[gn];
                    if (MODE == 1) {
                        if (gn >= 256) val += deg_emb[(size_t)dg * 256 + (gn - 256)];
                        C[(size_t)gm * NN + gn] = val;
                    } else if (MODE == 2) {
                        if (gn < 256) g_ab[(size_t)gm * 256 + gn] = val;
                        else          g_vb[(size_t)gm * 256 + (gn - 256)] = val;
                    } else {
                        C[(size_t)gm * NN + gn] = val;
                    }
                }
            }
        }
    }
}

// ---------------- edge counting sort -----------------------------------------
__global__ void zero_cnt() {
    int i = blockIdx.x * blockDim.x + threadIdx.x;
    if (i < NNODE) { g_cnt_g[i] = 0; g_cnt_l[i] = 0; }
}
__global__ void hist_k(const int* __restrict__ qi, const int* __restrict__ bond_idx) {
    int e = blockIdx.x * blockDim.x + threadIdx.x;
    if (e < EGLOBAL) atomicAdd(&g_cnt_g[qi[e]], 1);
    if (e < ELOCAL)  atomicAdd(&g_cnt_l[bond_idx[ELOCAL + e]], 1);
}
// one block per array: exclusive scan of 20000 counts (chunked Hillis-Steele)
__global__ void scan_k() {
    __shared__ int part[1024];
    int* cnt; int* off; int* cur;
    if (blockIdx.x == 0) { cnt = g_cnt_g; off = g_off_g; cur = g_cur_g; }
    else                 { cnt = g_cnt_l; off = g_off_l; cur = g_cur_l; }
    const int tid = threadIdx.x;
    const int chunk = (NNODE + 1023) / 1024;
    int lo = tid * chunk, hi = min(lo + chunk, NNODE);
    int s = 0;
    for (int i = lo; i < hi; i++) s += cnt[i];
    part[tid] = s;
    __syncthreads();
    for (int d = 1; d < 1024; d <<= 1) {
        int v = (tid >= d) ? part[tid - d] : 0;
        __syncthreads();
        part[tid] += v;
        __syncthreads();
    }
    int base = (tid > 0) ? part[tid - 1] : 0;
    for (int i = lo; i < hi; i++) {
        off[i] = base; cur[i] = base; base += cnt[i];
    }
    if (tid == 1023) off[NNODE] = part[1023];
}
__global__ void scat_k(const int* __restrict__ qi, const int* __restrict__ ki,
                       const int* __restrict__ dist, const int* __restrict__ bond_idx) {
    int e = blockIdx.x * blockDim.x + threadIdx.x;
    if (e < EGLOBAL) {
        int p = atomicAdd(&g_cur_g[qi[e]], 1);
        g_ep_g[p] = make_int4(ki[e], dist[e], e, 0);
    }
    if (e < ELOCAL) {
        int p = atomicAdd(&g_cur_l[bond_idx[ELOCAL + e]], 1);
        g_ep_l[p] = make_int2(bond_idx[e], e);
    }
}

// ---------------- local attention (sorted: block = dst node, no atomics) -----
__global__ void local_att_s()
{
    const int n = blockIdx.x, t = threadIdx.x;   // head = t>>5, dim = t&31
    const float qv = g_q[(size_t)n * 512 + t];
    float acc = 0.f, hsum = 0.f;
    const int p0 = g_off_l[n], p1 = g_off_l[n + 1];
    for (int p = p0; p < p1; p++) {
        int2 rec = g_ep_l[p];
        int src = rec.x, e = rec.y;
        float kv = g_k[(size_t)src * 512 + t];
        float vv = g_v[(size_t)src * 512 + t];
        float prod = qv * kv;
        if (e < EBOND) {
            prod += g_ab[(size_t)e * 256 + t];
            vv   += g_vb[(size_t)e * 256 + t];
        }
        float s = prod;
#pragma unroll
        for (int o = 16; o; o >>= 1) s += __shfl_xor_sync(0xffffffffu, s, o);
        float es = __expf(s * SCALE);
        acc += es * vv;
        hsum += es;
    }
    g_lacc[(size_t)n * 256 + t] = acc;
    if ((t & 31) == 0) g_lsum[n * HEADS + (t >> 5)] = hsum;
}

// ---------------- global attention (sorted: block = query node, no atomics) --
__global__ void global_att_s(const float* __restrict__ dist_emb)
{
    const int n = blockIdx.x, t = threadIdx.x;
    const float qv = g_q[(size_t)n * 512 + 256 + t];
    float acc = 0.f, hsum = 0.f;
    const int p0 = g_off_g[n], p1 = g_off_g[n + 1];
    for (int p = p0; p < p1; p++) {
        int4 rec = g_ep_g[p];
        int k = rec.x, dd = rec.y, e = rec.z;
        float prod = qv * g_k[(size_t)k * 512 + 256 + t]
                   + __ldg(&dist_emb[(size_t)dd * 256 + t]);
        if (e < EBOND) prod += g_ab[(size_t)e * 256 + t];
        float s = prod;
#pragma unroll
        for (int o = 16; o; o >>= 1) s += __shfl_xor_sync(0xffffffffu, s, o);
        float es = __expf(s * SCALE);
        acc += es * g_v[(size_t)k * 512 + 256 + t];
        hsum += es;
    }
    g_gacc[(size_t)n * 256 + t] = acc;
    if ((t & 31) == 0) g_gsum[n * HEADS + (t >> 5)] = hsum;
}

// ---------------- launch -----------------------------------------------------
extern "C" void kernel_launch(void* const* d_in, const int* in_sizes, int n_in,
                              void* d_out, int out_size)
{
    const float* f_node   = (const float*)d_in[0];
    const float* f_bond   = (const float*)d_in[1];
    const int*   deg      = (const int*)d_in[2];
    const int*   dist     = (const int*)d_in[3];
    const int*   bond_idx = (const int*)d_in[4];
    const int*   query_ix = (const int*)d_in[5];
    const int*   key_ix   = (const int*)d_in[6];
    // d_in[7] attention_bond_idx == arange(E_BOND) (positional identity)
    const float* deg_emb  = (const float*)d_in[8];
    const float* dist_emb = (const float*)d_in[9];
    const float* Wq_w = (const float*)d_in[10]; const float* Wq_b = (const float*)d_in[11];
    const float* Wk_w = (const float*)d_in[12]; const float* Wk_b = (const float*)d_in[13];
    const float* Wv_w = (const float*)d_in[14]; const float* Wv_b = (const float*)d_in[15];
    const float* out_w = (const float*)d_in[16]; const float* out_b = (const float*)d_in[17];
    const float* be_w = (const float*)d_in[18]; const float* be_b = (const float*)d_in[19];
    const float* bu_w = (const float*)d_in[20]; const float* bu_b = (const float*)d_in[21];

    float* out      = (float*)d_out;                      // (NNODE, 256)
    float* bond_out = out + (size_t)NNODE * 256;          // (EBOND, 256)

    // ---- edge sort pipeline (overlaps nothing; all tiny) ----
    zero_cnt<<<(NNODE + 255) / 256, 256>>>();
    hist_k<<<(EGLOBAL + 255) / 256, 256>>>(query_ix, bond_idx);
    scan_k<<<2, 1024>>>();
    scat_k<<<(EGLOBAL + 255) / 256, 256>>>(query_ix, key_ix, dist, bond_idx);

    dim3 gN512(512 / BNT, (NNODE + BMT - 1) / BMT);
    dim3 gE512(512 / BNT, (EBOND + BMT - 1) / BMT);
    dim3 gN256(256 / BNT, (NNODE + BMT - 1) / BMT);
    dim3 gE256(256 / BNT, (EBOND + BMT - 1) / BMT);

    // q/k/v: M=NNODE, K=256, NN=512 (destinations resolved device-side by MODE)
    tgemm<0><<<gN512, 256>>>(NNODE, 256, 512, f_node, Wq_w, Wq_b, nullptr,
                             nullptr, nullptr, nullptr, nullptr);
    tgemm<1><<<gN512, 256>>>(NNODE, 256, 512, f_node, Wk_w, Wk_b, nullptr,
                             nullptr, nullptr, deg, deg_emb);
    tgemm<5><<<gN512, 256>>>(NNODE, 256, 512, f_node, Wv_w, Wv_b, nullptr,
                             nullptr, nullptr, nullptr, nullptr);

    // bond embedding: M=EBOND, K=256, NN=512 -> g_ab / g_vb (device-internal)
    tgemm<2><<<gE512, 256>>>(EBOND, 256, 512, f_bond, be_w, be_b, nullptr,
                             nullptr, nullptr, nullptr, nullptr);

    local_att_s<<<NNODE, 256>>>();
    global_att_s<<<NNODE, 256>>>(dist_emb);

    // out = [lacc/lsum | gacc/gsum] @ out_w + out_b : M=NNODE, K=512, NN=256
    tgemm<3><<<gN256, 256>>>(NNODE, 512, 256, nullptr, out_w, out_b, out,
                             nullptr, nullptr, nullptr, nullptr);

    // bond_out = [f_bond | out[src]] @ bu_w + bu_b : M=EBOND, K=512, NN=256
    tgemm<4><<<gE256, 256>>>(EBOND, 512, 256, f_bond, bu_w, bu_b, bond_out,
                             bond_idx, out, nullptr, nullptr);
}